// round 5
// baseline (speedup 1.0000x reference)
#include <cuda_runtime.h>
#include <cuda_bf16.h>
#include <cstdint>

// ---------------- problem constants ----------------
#define BATCH 2
#define CCH   256
#define NSP   32768
#define NHEAD 8
#define HD    32
#define GRP   32
#define CPG   8
#define MQKV  768
#define EPS   1e-5f
#define KVSPLIT 64

// ---------------- static scratch ----------------
__device__ float g_qkv[(size_t)BATCH * MQKV * NSP];
__device__ float g_proj[(size_t)BATCH * CCH * NSP];
__device__ float g_mu1[BATCH * GRP];
__device__ float g_rstd1[BATCH * GRP];
__device__ float g_mu2[BATCH * GRP];
__device__ float g_rstd2[BATCH * GRP];
__device__ float g_scale1[BATCH * CCH];
__device__ float g_shift1[BATCH * CCH];
__device__ float g_a2[(size_t)BATCH * MQKV * CCH];    // folded+tf32-rounded A' (per batch)
__device__ float g_bias2[BATCH * MQKV];
__device__ float g_ow[CCH * CCH];                     // tf32-rounded out_w
__device__ float g_ksumA[BATCH * CCH];
__device__ float g_kvpart[(size_t)KVSPLIT * 16 * 1024];
__device__ float g_ksump[KVSPLIT * 16 * 32];
__device__ float g_kv[BATCH * NHEAD * HD * HD];

// ---------------- helpers ----------------
__device__ __forceinline__ float warp_sum(float v) {
    #pragma unroll
    for (int o = 16; o; o >>= 1) v += __shfl_xor_sync(0xffffffffu, v, o);
    return v;
}
__device__ __forceinline__ float to_tf32(float x) {
    uint32_t u;
    asm("cvt.rna.tf32.f32 %0, %1;" : "=r"(u) : "f"(x));
    return __uint_as_float(u);
}
__device__ __forceinline__ uint32_t smem_u32(const void* p) {
    uint32_t a;
    asm("{ .reg .u64 t; cvta.to.shared.u64 t, %1; cvt.u32.u64 %0, t; }" : "=r"(a) : "l"(p));
    return a;
}
__device__ __forceinline__ void cp16(uint32_t saddr, const void* g) {
    asm volatile("cp.async.ca.shared.global [%0], [%1], 16;" :: "r"(saddr), "l"(g) : "memory");
}
__device__ __forceinline__ void cp_commit() {
    asm volatile("cp.async.commit_group;" ::: "memory");
}
__device__ __forceinline__ void cp_wait0() {
    asm volatile("cp.async.wait_group 0;" ::: "memory");
}

__device__ __forceinline__ void mma_tf32(
    float& c0, float& c1, float& c2, float& c3,
    float a0, float a1, float a2, float a3,
    float b0, float b1)
{
    asm volatile(
        "mma.sync.aligned.m16n8k8.row.col.f32.tf32.tf32.f32 "
        "{%0,%1,%2,%3}, {%4,%5,%6,%7}, {%8,%9}, {%0,%1,%2,%3};"
        : "+f"(c0), "+f"(c1), "+f"(c2), "+f"(c3)
        : "r"(__float_as_uint(a0)), "r"(__float_as_uint(a1)),
          "r"(__float_as_uint(a2)), "r"(__float_as_uint(a3)),
          "r"(__float_as_uint(b0)), "r"(__float_as_uint(b1)));
}

// ---------------- group-norm stats ----------------
template<int STAGE>
__global__ void gn_stats_kernel(const float* __restrict__ xsrc) {
    const float* src = (STAGE == 0) ? xsrc : g_proj;
    int grp = blockIdx.x;
    const float4* base = (const float4*)(src + (size_t)grp * CPG * NSP);
    const int M4 = CPG * NSP / 4;
    float s = 0.f, s2 = 0.f;
    for (int i = threadIdx.x; i < M4; i += 256) {
        float4 v = base[i];
        s  += (v.x + v.y) + (v.z + v.w);
        s2 += v.x * v.x + v.y * v.y + v.z * v.z + v.w * v.w;
    }
    __shared__ float sh[8], sh2[8];
    s = warp_sum(s); s2 = warp_sum(s2);
    int w = threadIdx.x >> 5, l = threadIdx.x & 31;
    if (l == 0) { sh[w] = s; sh2[w] = s2; }
    __syncthreads();
    if (w == 0) {
        s  = (l < 8) ? sh[l]  : 0.f;
        s2 = (l < 8) ? sh2[l] : 0.f;
        s = warp_sum(s); s2 = warp_sum(s2);
        if (l == 0) {
            const float inv = 1.0f / (float)(CPG * NSP);
            float mu  = s * inv;
            float var = s2 * inv - mu * mu;
            float rs  = rsqrtf(var + EPS);
            if (STAGE == 0) { g_mu1[grp] = mu; g_rstd1[grp] = rs; }
            else            { g_mu2[grp] = mu; g_rstd2[grp] = rs; }
        }
    }
}

__global__ void prep_kernel(const float* __restrict__ nw, const float* __restrict__ nb) {
    int i = blockIdx.x * 256 + threadIdx.x;
    if (i < BATCH * CCH) {
        int b = i / CCH, c = i % CCH;
        float mu = g_mu1[b * GRP + c / CPG];
        float r  = g_rstd1[b * GRP + c / CPG];
        float sc = r * nw[c];
        g_scale1[i] = sc;
        g_shift1[i] = nb[c] - mu * sc;
    }
}

// fold GN1 affine into weights (tf32-rounded): A' = rna(W*sc), bias' = W@sh + qkv_b
__global__ void prep2_kernel(const float* __restrict__ qkv_w, const float* __restrict__ qkv_b) {
    int o = blockIdx.x, b = blockIdx.y;
    int c = threadIdx.x;
    float w  = qkv_w[o * CCH + c];
    float sc = g_scale1[b * CCH + c];
    float sh = g_shift1[b * CCH + c];
    g_a2[((size_t)b * MQKV + o) * CCH + c] = to_tf32(w * sc);
    float v = w * sh;
    __shared__ float red[8];
    v = warp_sum(v);
    int wp = c >> 5, l = c & 31;
    if (l == 0) red[wp] = v;
    __syncthreads();
    if (c == 0) {
        float s = 0.f;
        #pragma unroll
        for (int i = 0; i < 8; i++) s += red[i];
        g_bias2[b * MQKV + o] = s + qkv_b[o];
    }
}

__global__ void prep_ow_kernel(const float* __restrict__ out_w) {
    int i = blockIdx.x * 256 + threadIdx.x;
    if (i < CCH * CCH) g_ow[i] = to_tf32(out_w[i]);
}

// ======== tf32 mma.sync GEMM, block 128x256, warp 64x64, cp.async double-buffer ====
// C[M,NSP] = A[M,256] @ B[256,NSP] + bias
// MODE 0: A=g_a2[bz] (pre-rounded), B=x[bz], C=g_qkv[bz], elu+1 on rows<512
// MODE 1: A=g_ow (pre-rounded),     B=q region, C=g_proj[bz]
#define BM 128
#define BN 256
#define LDA 40
#define LDB 260
#define ACHUNK (BM * LDA)
#define BCHUNK (32 * LDB)
#define SMEM_BYTES ((2 * ACHUNK + 2 * BCHUNK) * 4)   // 107520

template<int MODE>
__global__ void __launch_bounds__(256) mma_gemm_kernel(
    const float* __restrict__ Bsrc, const float* __restrict__ bias_arg)
{
    extern __shared__ float smf[];
    const uint32_t sbase = smem_u32(smf);
    float* Asm[2] = { smf,              smf + ACHUNK };
    float* Bsm[2] = { smf + 2*ACHUNK,   smf + 2*ACHUNK + BCHUNK };
    const uint32_t aAddr[2] = { sbase,                       sbase + ACHUNK*4 };
    const uint32_t bAddr[2] = { sbase + 2*ACHUNK*4,          sbase + (2*ACHUNK + BCHUNK)*4 };

    const int bz = blockIdx.z;
    const int mt = blockIdx.y;
    const int nt = blockIdx.x;
    const int t  = threadIdx.x;
    const int warp = t >> 5, lane = t & 31;
    const int wm = warp >> 2;        // 0..1  -> rows wm*64
    const int wn = warp & 3;         // 0..3  -> cols wn*64
    const int g  = lane >> 2;        // 0..7
    const int c  = lane & 3;         // 0..3

    const float* Ab;
    const float* Bb;
    const float* bias;
    float* Cd;
    if (MODE == 0) {
        Ab   = g_a2 + (size_t)bz * MQKV * CCH + (size_t)mt * BM * CCH;
        bias = g_bias2 + bz * MQKV;
        Bb   = Bsrc + (size_t)bz * CCH * NSP + (size_t)nt * BN;
        Cd   = g_qkv + ((size_t)bz * MQKV + (size_t)mt * BM) * NSP + (size_t)nt * BN;
    } else {
        Ab   = g_ow + (size_t)mt * BM * CCH;
        bias = bias_arg;
        Bb   = g_qkv + (size_t)bz * MQKV * NSP + (size_t)nt * BN;
        Cd   = g_proj + ((size_t)bz * CCH + (size_t)mt * BM) * NSP + (size_t)nt * BN;
    }

    float acc[4][8][4];
    #pragma unroll
    for (int i = 0; i < 4; i++)
        #pragma unroll
        for (int j = 0; j < 8; j++)
            #pragma unroll
            for (int q = 0; q < 4; q++) acc[i][j][q] = 0.f;

    // chunk loader: A 128x32 (4 cp16/thr), B 32x256 (8 cp16/thr)
    auto load_chunk = [&](int ch, int buf) {
        #pragma unroll
        for (int i = 0; i < 4; i++) {
            int f = t + i * 256;
            int m = f >> 3, c4 = f & 7;
            cp16(aAddr[buf] + (uint32_t)(m * LDA + c4 * 4) * 4,
                 Ab + (size_t)m * CCH + ch * 32 + c4 * 4);
        }
        #pragma unroll
        for (int i = 0; i < 8; i++) {
            int f = t + i * 256;
            int k = f >> 6, n4 = f & 63;
            cp16(bAddr[buf] + (uint32_t)(k * LDB + n4 * 4) * 4,
                 Bb + (size_t)(ch * 32 + k) * NSP + n4 * 4);
        }
        cp_commit();
    };

    load_chunk(0, 0);

    // fragment bases. k-permutation: logical (c, c+4) <-> physical (2c, 2c+1),
    // applied identically to A and B => mma result unchanged, A pair contiguous.
    const int a_row0 = wm * 64 + g;                  // + i2*16, +8
    const int b_col  = wn * 64 + g;                  // + j2*8

    #pragma unroll 1
    for (int kt = 0; kt < 8; kt++) {
        int b = kt & 1;
        cp_wait0();
        __syncthreads();
        if (kt < 7) load_chunk(kt + 1, 1 - b);

        const float* As = Asm[b];
        const float* Bs = Bsm[b];
        #pragma unroll
        for (int kg = 0; kg < 4; kg++) {
            const int kb = kg * 8;
            // A fragments: 4 m-tiles x 2 LDS.64 (physical k = kb+2c, kb+2c+1)
            float2 afe[4], afo[4];
            #pragma unroll
            for (int i2 = 0; i2 < 4; i2++) {
                int r0 = a_row0 + i2 * 16;
                afe[i2] = *(const float2*)&As[r0 * LDA + kb + 2 * c];
                afo[i2] = *(const float2*)&As[(r0 + 8) * LDA + kb + 2 * c];
            }
            #pragma unroll
            for (int j2 = 0; j2 < 8; j2++) {
                float b0 = to_tf32(Bs[(kb + 2 * c) * LDB + b_col + j2 * 8]);
                float b1 = to_tf32(Bs[(kb + 2 * c + 1) * LDB + b_col + j2 * 8]);
                #pragma unroll
                for (int i2 = 0; i2 < 4; i2++)
                    mma_tf32(acc[i2][j2][0], acc[i2][j2][1], acc[i2][j2][2], acc[i2][j2][3],
                             afe[i2].x, afo[i2].x, afe[i2].y, afo[i2].y, b0, b1);
            }
        }
        __syncthreads();
    }

    // epilogue
    #pragma unroll
    for (int i2 = 0; i2 < 4; i2++) {
        int lr0 = wm * 64 + i2 * 16 + g;
        int o0  = mt * BM + lr0;
        int o1  = o0 + 8;
        float bi0 = bias[o0], bi1 = bias[o1];
        #pragma unroll
        for (int j2 = 0; j2 < 8; j2++) {
            int lc = wn * 64 + j2 * 8 + 2 * c;
            float v0 = acc[i2][j2][0] + bi0;
            float v1 = acc[i2][j2][1] + bi0;
            float v2 = acc[i2][j2][2] + bi1;
            float v3 = acc[i2][j2][3] + bi1;
            if (MODE == 0 && o0 < 512) {
                v0 = (v0 > 0.f) ? (v0 + 1.f) : __expf(v0);
                v1 = (v1 > 0.f) ? (v1 + 1.f) : __expf(v1);
            }
            if (MODE == 0 && o1 < 512) {
                v2 = (v2 > 0.f) ? (v2 + 1.f) : __expf(v2);
                v3 = (v3 > 0.f) ? (v3 + 1.f) : __expf(v3);
            }
            *(float2*)(Cd + (size_t)lr0 * NSP + lc)       = make_float2(v0, v1);
            *(float2*)(Cd + (size_t)(lr0 + 8) * NSP + lc) = make_float2(v2, v3);
        }
    }
}

// ---------------- kv partials + k rowsum partials (fused) ----------------
__global__ void __launch_bounds__(256) kv_kernel() {
    int bh = blockIdx.x;
    int split = blockIdx.y;
    int b = bh >> 3, h = bh & 7;

    __shared__ float ks[32][129];
    __shared__ float vs[32][129];

    const float* kbase = g_qkv + ((size_t)b * MQKV + 256 + h * HD) * NSP + (size_t)split * 512;
    const float* vbase = g_qkv + ((size_t)b * MQKV + 512 + h * HD) * NSP + (size_t)split * 512;

    int t = threadIdx.x;
    int d0 = (t >> 4) << 1;
    int e0 = (t & 15) << 1;

    float a00 = 0.f, a01 = 0.f, a10 = 0.f, a11 = 0.f;
    float s0 = 0.f, s1 = 0.f;

    for (int ch = 0; ch < 4; ch++) {
        __syncthreads();
        #pragma unroll
        for (int it = 0; it < 4; it++) {
            int f = t + it * 256;
            int dr = f >> 5, dc = (f & 31) << 2;
            float4 kk = *(const float4*)(kbase + (size_t)dr * NSP + ch * 128 + dc);
            ks[dr][dc + 0] = kk.x; ks[dr][dc + 1] = kk.y;
            ks[dr][dc + 2] = kk.z; ks[dr][dc + 3] = kk.w;
            float4 vv = *(const float4*)(vbase + (size_t)dr * NSP + ch * 128 + dc);
            vs[dr][dc + 0] = vv.x; vs[dr][dc + 1] = vv.y;
            vs[dr][dc + 2] = vv.z; vs[dr][dc + 3] = vv.w;
        }
        __syncthreads();
        #pragma unroll 4
        for (int n = 0; n < 128; n++) {
            float k0v = ks[d0][n],     k1v = ks[d0 + 1][n];
            float v0v = vs[e0][n],     v1v = vs[e0 + 1][n];
            a00 = fmaf(k0v, v0v, a00); a01 = fmaf(k0v, v1v, a01);
            a10 = fmaf(k1v, v0v, a10); a11 = fmaf(k1v, v1v, a11);
            s0 += k0v; s1 += k1v;
        }
    }

    float* dst = g_kvpart + ((size_t)split * 16 + bh) * 1024;
    dst[(d0    ) * 32 + e0    ] = a00;
    dst[(d0    ) * 32 + e0 + 1] = a01;
    dst[(d0 + 1) * 32 + e0    ] = a10;
    dst[(d0 + 1) * 32 + e0 + 1] = a11;
    if (e0 == 0) {
        g_ksump[(split * 16 + bh) * 32 + d0]     = s0;
        g_ksump[(split * 16 + bh) * 32 + d0 + 1] = s1;
    }
}

__global__ void kvreduce_kernel() {
    int i = blockIdx.x * 256 + threadIdx.x;
    if (i >= 16 * 1024) return;
    int bh = i >> 10, de = i & 1023;
    int d = de >> 5, e = de & 31;
    float rs = 0.f;
    #pragma unroll 8
    for (int sp = 0; sp < KVSPLIT; sp++)
        rs += g_ksump[(sp * 16 + bh) * 32 + d];
    float cs = fmaxf(rs, 1e-6f);
    float inv = 1.0f / cs;
    float s = 0.f;
    #pragma unroll 8
    for (int sp = 0; sp < KVSPLIT; sp++)
        s += g_kvpart[((size_t)sp * 16 + bh) * 1024 + de];
    g_kv[i] = s * inv;
    if (e == 0) {
        int b = bh >> 3, h = bh & 7;
        g_ksumA[b * CCH + h * HD + d] = rs * inv;
    }
}

// ---------------- out = kv^T·q / clip(normalizer); overwrites q in place ----------
__global__ void __launch_bounds__(256) attnout_kernel() {
    int nblk = blockIdx.x;
    int bh = blockIdx.y;
    int b = bh >> 3, h = bh & 7;

    __shared__ float qs[32][128];
    __shared__ float kvs[32][32];
    __shared__ float ksA[32];

    int t = threadIdx.x;
    float* qbase = g_qkv + ((size_t)b * MQKV + h * HD) * NSP + (size_t)nblk * 128;

    #pragma unroll
    for (int it = 0; it < 4; it++) {
        int f = t + it * 256;
        int dr = f >> 5, dc = (f & 31) << 2;
        *(float4*)&qs[dr][dc] = *(const float4*)(qbase + (size_t)dr * NSP + dc);
    }
    #pragma unroll
    for (int it = 0; it < 4; it++)
        ((float*)kvs)[t + it * 256] = g_kv[bh * 1024 + t + it * 256];
    if (t < 32) ksA[t] = g_ksumA[b * CCH + h * HD + t];
    __syncthreads();

    int n  = t & 127;
    int e0 = (t >> 7) << 4;

    float norm = 0.f;
    #pragma unroll
    for (int d = 0; d < 32; d++) norm = fmaf(qs[d][n], ksA[d], norm);
    float rn = 1.0f / fmaxf(norm, 1e-6f);

    float acc[16];
    #pragma unroll
    for (int e = 0; e < 16; e++) acc[e] = 0.f;
    #pragma unroll
    for (int d = 0; d < 32; d++) {
        float qd = qs[d][n];
        #pragma unroll
        for (int e = 0; e < 16; e++)
            acc[e] = fmaf(qd, kvs[d][e0 + e], acc[e]);
    }
    #pragma unroll
    for (int e = 0; e < 16; e++)
        qbase[(size_t)(e0 + e) * NSP + n] = acc[e] * rn;
}

// ---------------- final: y = x + GN2(proj) ----------------
__global__ void final_kernel(const float* __restrict__ x,
                             const float* __restrict__ ow, const float* __restrict__ ob,
                             float* __restrict__ out) {
    const int n4 = NSP / 4;
    const int total = BATCH * CCH * n4;
    for (int i = blockIdx.x * blockDim.x + threadIdx.x; i < total; i += gridDim.x * blockDim.x) {
        int row = i / n4;
        int c = row % CCH, b = row / CCH;
        int g = c / CPG;
        float mu = g_mu2[b * GRP + g], r = g_rstd2[b * GRP + g];
        float sc = r * ow[c];
        float sh = ob[c] - mu * sc;
        float4 xv = ((const float4*)x)[i];
        float4 pv = ((const float4*)g_proj)[i];
        float4 o;
        o.x = xv.x + fmaf(pv.x, sc, sh);
        o.y = xv.y + fmaf(pv.y, sc, sh);
        o.z = xv.z + fmaf(pv.z, sc, sh);
        o.w = xv.w + fmaf(pv.w, sc, sh);
        ((float4*)out)[i] = o;
    }
}

// ---------------- launch ----------------
extern "C" void kernel_launch(void* const* d_in, const int* in_sizes, int n_in,
                              void* d_out, int out_size) {
    const float* x      = (const float*)d_in[0];
    const float* norm_w = (const float*)d_in[1];
    const float* norm_b = (const float*)d_in[2];
    const float* qkv_w  = (const float*)d_in[3];
    const float* qkv_b  = (const float*)d_in[4];
    const float* out_w  = (const float*)d_in[5];
    const float* out_b  = (const float*)d_in[6];
    const float* onw    = (const float*)d_in[7];
    const float* onb    = (const float*)d_in[8];
    float* out = (float*)d_out;

    cudaFuncSetAttribute(mma_gemm_kernel<0>, cudaFuncAttributeMaxDynamicSharedMemorySize, SMEM_BYTES);
    cudaFuncSetAttribute(mma_gemm_kernel<1>, cudaFuncAttributeMaxDynamicSharedMemorySize, SMEM_BYTES);

    gn_stats_kernel<0><<<BATCH * GRP, 256>>>(x);
    prep_kernel<<<2, 256>>>(norm_w, norm_b);
    prep2_kernel<<<dim3(MQKV, BATCH), 256>>>(qkv_w, qkv_b);
    prep_ow_kernel<<<256, 256>>>(out_w);
    mma_gemm_kernel<0><<<dim3(NSP / BN, MQKV / BM, BATCH), 256, SMEM_BYTES>>>(x, nullptr);
    kv_kernel<<<dim3(16, KVSPLIT), 256>>>();
    kvreduce_kernel<<<64, 256>>>();
    attnout_kernel<<<dim3(NSP / 128, 16), 256>>>();
    mma_gemm_kernel<1><<<dim3(NSP / BN, CCH / BM, BATCH), 256, SMEM_BYTES>>>(nullptr, out_b);
    gn_stats_kernel<1><<<BATCH * GRP, 256>>>(x /*unused*/);
    final_kernel<<<4096, 256>>>(x, onw, onb, out);
}

// round 6
// speedup vs baseline: 1.3532x; 1.3532x over previous
#include <cuda_runtime.h>
#include <cuda_fp16.h>
#include <cstdint>

// ---------------- problem constants ----------------
#define BATCH 2
#define CCH   256
#define NSP   32768
#define NHEAD 8
#define HD    32
#define GRP   32
#define CPG   8
#define MQKV  768
#define EPS   1e-5f
#define KVSPLIT 64

// ---------------- static scratch ----------------
__device__ __half g_qkvh[(size_t)BATCH * MQKV * NSP];   // 96 MB fp16 q|k|v
__device__ __half g_xh[(size_t)BATCH * CCH * NSP];      // 32 MB fp16 x
__device__ __half g_outh[(size_t)BATCH * CCH * NSP];    // 32 MB fp16 attn out
__device__ float  g_proj[(size_t)BATCH * CCH * NSP];    // 64 MB fp32
__device__ __half g_a2h[(size_t)BATCH * MQKV * CCH];    // folded A' fp16
__device__ __half g_owh[CCH * CCH];                     // out_w fp16
__device__ float g_mu1[BATCH * GRP];
__device__ float g_rstd1[BATCH * GRP];
__device__ float g_mu2[BATCH * GRP];
__device__ float g_rstd2[BATCH * GRP];
__device__ float g_scale1[BATCH * CCH];
__device__ float g_shift1[BATCH * CCH];
__device__ float g_bias2[BATCH * MQKV];
__device__ float g_ksumA[BATCH * CCH];
__device__ float g_kvpart[(size_t)KVSPLIT * 16 * 1024];
__device__ float g_ksump[KVSPLIT * 16 * 32];
__device__ float g_kv[BATCH * NHEAD * HD * HD];

// ---------------- helpers ----------------
__device__ __forceinline__ float warp_sum(float v) {
    #pragma unroll
    for (int o = 16; o; o >>= 1) v += __shfl_xor_sync(0xffffffffu, v, o);
    return v;
}
__device__ __forceinline__ uint32_t smem_u32(const void* p) {
    uint32_t a;
    asm("{ .reg .u64 t; cvta.to.shared.u64 t, %1; cvt.u32.u64 %0, t; }" : "=r"(a) : "l"(p));
    return a;
}
__device__ __forceinline__ void cp16(uint32_t saddr, const void* g) {
    asm volatile("cp.async.ca.shared.global [%0], [%1], 16;" :: "r"(saddr), "l"(g) : "memory");
}
__device__ __forceinline__ void cp_commit() {
    asm volatile("cp.async.commit_group;" ::: "memory");
}
__device__ __forceinline__ void cp_wait0() {
    asm volatile("cp.async.wait_group 0;" ::: "memory");
}
__device__ __forceinline__ void ldm_x4(uint32_t* r, uint32_t addr) {
    asm volatile("ldmatrix.sync.aligned.m8n8.x4.shared.b16 {%0,%1,%2,%3}, [%4];"
        : "=r"(r[0]), "=r"(r[1]), "=r"(r[2]), "=r"(r[3]) : "r"(addr));
}
__device__ __forceinline__ void ldm_x4_trans(uint32_t* r, uint32_t addr) {
    asm volatile("ldmatrix.sync.aligned.m8n8.x4.trans.shared.b16 {%0,%1,%2,%3}, [%4];"
        : "=r"(r[0]), "=r"(r[1]), "=r"(r[2]), "=r"(r[3]) : "r"(addr));
}
__device__ __forceinline__ void mma_fp16(float* c, const uint32_t* a, uint32_t b0, uint32_t b1) {
    asm volatile(
        "mma.sync.aligned.m16n8k16.row.col.f32.f16.f16.f32 "
        "{%0,%1,%2,%3}, {%4,%5,%6,%7}, {%8,%9}, {%0,%1,%2,%3};"
        : "+f"(c[0]), "+f"(c[1]), "+f"(c[2]), "+f"(c[3])
        : "r"(a[0]), "r"(a[1]), "r"(a[2]), "r"(a[3]), "r"(b0), "r"(b1));
}

// ---------------- group-norm stats (STAGE 0 also emits x as fp16) ----------------
template<int STAGE>
__global__ void gn_stats_kernel(const float* __restrict__ xsrc) {
    const float* src = (STAGE == 0) ? xsrc : g_proj;
    int grp = blockIdx.x;
    const float4* base = (const float4*)(src + (size_t)grp * CPG * NSP);
    uint2* xh4 = (uint2*)(g_xh + (size_t)grp * CPG * NSP);
    const int M4 = CPG * NSP / 4;
    float s = 0.f, s2 = 0.f;
    for (int i = threadIdx.x; i < M4; i += 256) {
        float4 v = base[i];
        s  += (v.x + v.y) + (v.z + v.w);
        s2 += v.x * v.x + v.y * v.y + v.z * v.z + v.w * v.w;
        if (STAGE == 0) {
            __half2 h0 = __floats2half2_rn(v.x, v.y);
            __half2 h1 = __floats2half2_rn(v.z, v.w);
            uint2 u;
            u.x = *(uint32_t*)&h0;
            u.y = *(uint32_t*)&h1;
            xh4[i] = u;
        }
    }
    __shared__ float sh[8], sh2[8];
    s = warp_sum(s); s2 = warp_sum(s2);
    int w = threadIdx.x >> 5, l = threadIdx.x & 31;
    if (l == 0) { sh[w] = s; sh2[w] = s2; }
    __syncthreads();
    if (w == 0) {
        s  = (l < 8) ? sh[l]  : 0.f;
        s2 = (l < 8) ? sh2[l] : 0.f;
        s = warp_sum(s); s2 = warp_sum(s2);
        if (l == 0) {
            const float inv = 1.0f / (float)(CPG * NSP);
            float mu  = s * inv;
            float var = s2 * inv - mu * mu;
            float rs  = rsqrtf(var + EPS);
            if (STAGE == 0) { g_mu1[grp] = mu; g_rstd1[grp] = rs; }
            else            { g_mu2[grp] = mu; g_rstd2[grp] = rs; }
        }
    }
}

__global__ void prep_kernel(const float* __restrict__ nw, const float* __restrict__ nb) {
    int i = blockIdx.x * 256 + threadIdx.x;
    if (i < BATCH * CCH) {
        int b = i / CCH, c = i % CCH;
        float mu = g_mu1[b * GRP + c / CPG];
        float r  = g_rstd1[b * GRP + c / CPG];
        float sc = r * nw[c];
        g_scale1[i] = sc;
        g_shift1[i] = nb[c] - mu * sc;
    }
}

// fold GN1 affine into weights: A' = fp16(W*sc), bias' = W@sh + qkv_b
__global__ void prep2_kernel(const float* __restrict__ qkv_w, const float* __restrict__ qkv_b) {
    int o = blockIdx.x, b = blockIdx.y;
    int c = threadIdx.x;
    float w  = qkv_w[o * CCH + c];
    float sc = g_scale1[b * CCH + c];
    float sh = g_shift1[b * CCH + c];
    g_a2h[((size_t)b * MQKV + o) * CCH + c] = __float2half_rn(w * sc);
    float v = w * sh;
    __shared__ float red[8];
    v = warp_sum(v);
    int wp = c >> 5, l = c & 31;
    if (l == 0) red[wp] = v;
    __syncthreads();
    if (c == 0) {
        float s = 0.f;
        #pragma unroll
        for (int i = 0; i < 8; i++) s += red[i];
        g_bias2[b * MQKV + o] = s + qkv_b[o];
    }
}

__global__ void prep_ow_kernel(const float* __restrict__ out_w) {
    int i = blockIdx.x * 256 + threadIdx.x;
    if (i < CCH * CCH) g_owh[i] = __float2half_rn(out_w[i]);
}

// ======== fp16 mma.sync m16n8k16 GEMM, ldmatrix, cp.async double-buffer ========
// C[M,NSP] = A[M,256] @ B[256,NSP] + bias.  Block 128x128, warp 32x64.
// MODE 0: A=g_a2h[bz], B=g_xh[bz], C=g_qkvh fp16 (elu+1 rows<512)
// MODE 1: A=g_owh,     B=g_outh[bz], C=g_proj fp32
// Smem per buf: A 128rows x 64B (swz chunk ^= (row>>1)&3), B 32rows x 256B (swz chunk ^= k&7)
#define ABUF 8192
#define BBUF 8192

template<int MODE>
__global__ void __launch_bounds__(256) mma_gemm_kernel(const float* __restrict__ bias_arg)
{
    __shared__ __align__(128) char smem[2 * ABUF + 2 * BBUF];
    const uint32_t sbase = smem_u32(smem);
    const uint32_t aOff[2] = { 0u, ABUF };
    const uint32_t bOff[2] = { 2u * ABUF, 2u * ABUF + BBUF };

    const int bz = blockIdx.z;
    const int mt = blockIdx.y;
    const int nt = blockIdx.x;
    const int t  = threadIdx.x;
    const int warp = t >> 5, lane = t & 31;
    const int wm = warp >> 1;        // 0..3 : rows wm*32
    const int wn = warp & 1;         // 0..1 : cols wn*64
    const int g  = lane >> 2;
    const int c  = lane & 3;

    const __half* Ab;
    const __half* Bb;
    const float* bias;
    if (MODE == 0) {
        Ab   = g_a2h + (size_t)bz * MQKV * CCH + (size_t)mt * 128 * CCH;
        bias = g_bias2 + bz * MQKV;
        Bb   = g_xh + (size_t)bz * CCH * NSP + (size_t)nt * 128;
    } else {
        Ab   = g_owh + (size_t)mt * 128 * CCH;
        bias = bias_arg;
        Bb   = g_outh + (size_t)bz * CCH * NSP + (size_t)nt * 128;
    }

    float acc[2][8][4];
    #pragma unroll
    for (int i = 0; i < 2; i++)
        #pragma unroll
        for (int j = 0; j < 8; j++)
            #pragma unroll
            for (int q = 0; q < 4; q++) acc[i][j][q] = 0.f;

    // loaders: A 128x32h (512 cp16, 2/thr), B 32x128h (512 cp16, 2/thr)
    auto load_chunk = [&](int ch, int buf) {
        #pragma unroll
        for (int i = 0; i < 2; i++) {
            int f = t + i * 256;
            int m = f >> 2, k8 = f & 3;
            uint32_t dst = sbase + aOff[buf] + (uint32_t)(m * 64 + (((k8) ^ ((m >> 1) & 3)) << 4));
            cp16(dst, Ab + (size_t)m * CCH + ch * 32 + k8 * 8);
        }
        #pragma unroll
        for (int i = 0; i < 2; i++) {
            int f = t + i * 256;
            int k = f >> 4, cc = f & 15;
            uint32_t dst = sbase + bOff[buf] + (uint32_t)(k * 256 + ((cc ^ (k & 7)) << 4));
            cp16(dst, Bb + (size_t)(ch * 32 + k) * NSP + cc * 8);
        }
        cp_commit();
    };

    load_chunk(0, 0);

    // ldmatrix lane addresses (kg=0 bases)
    uint32_t aAddrF[2];
    {
        int row_lo = (lane & 7) + ((lane >> 3) & 1) * 8;
        int kc = lane >> 4;                       // 0 or 1
        #pragma unroll
        for (int i2 = 0; i2 < 2; i2++) {
            int row = wm * 32 + i2 * 16 + row_lo;
            aAddrF[i2] = (uint32_t)(row * 64 + ((kc ^ ((row >> 1) & 3)) << 4));
        }
    }
    uint32_t bAddrF;
    {
        int k  = (lane & 7) + ((lane >> 4) << 3);     // 0..15
        int nb = wn * 64 + ((lane >> 3) & 1) * 8;
        int cc = nb >> 3;
        bAddrF = (uint32_t)(k * 256 + ((cc ^ (k & 7)) << 4));
    }

    #pragma unroll 1
    for (int kt = 0; kt < 8; kt++) {
        int buf = kt & 1;
        cp_wait0();
        __syncthreads();
        if (kt < 7) load_chunk(kt + 1, 1 - buf);

        #pragma unroll
        for (int kg = 0; kg < 2; kg++) {
            uint32_t afr[2][4];
            #pragma unroll
            for (int i2 = 0; i2 < 2; i2++)
                ldm_x4(afr[i2], sbase + aOff[buf] + (aAddrF[i2] ^ (kg << 5)));
            uint32_t bfr[4][4];
            #pragma unroll
            for (int j4 = 0; j4 < 4; j4++)
                ldm_x4_trans(bfr[j4], sbase + bOff[buf] + ((bAddrF ^ (j4 << 5)) + (kg << 12)));
            #pragma unroll
            for (int j2 = 0; j2 < 8; j2++) {
                uint32_t b0 = bfr[j2 >> 1][(j2 & 1)];
                uint32_t b1 = bfr[j2 >> 1][(j2 & 1) + 2];
                #pragma unroll
                for (int i2 = 0; i2 < 2; i2++)
                    mma_fp16(acc[i2][j2], afr[i2], b0, b1);
            }
        }
        __syncthreads();
    }

    // epilogue
    #pragma unroll
    for (int i2 = 0; i2 < 2; i2++) {
        int lr0 = wm * 32 + i2 * 16 + g;
        int o0  = mt * 128 + lr0;
        int o1  = o0 + 8;
        float bi0 = bias[o0], bi1 = bias[o1];
        #pragma unroll
        for (int j2 = 0; j2 < 8; j2++) {
            int lc = wn * 64 + j2 * 8 + 2 * c;
            float v0 = acc[i2][j2][0] + bi0;
            float v1 = acc[i2][j2][1] + bi0;
            float v2 = acc[i2][j2][2] + bi1;
            float v3 = acc[i2][j2][3] + bi1;
            if (MODE == 0) {
                if (o0 < 512) {
                    v0 = (v0 > 0.f) ? (v0 + 1.f) : __expf(v0);
                    v1 = (v1 > 0.f) ? (v1 + 1.f) : __expf(v1);
                }
                if (o1 < 512) {
                    v2 = (v2 > 0.f) ? (v2 + 1.f) : __expf(v2);
                    v3 = (v3 > 0.f) ? (v3 + 1.f) : __expf(v3);
                }
                __half* Cd = g_qkvh + ((size_t)bz * MQKV + (size_t)mt * 128) * NSP + (size_t)nt * 128;
                __half2 h01 = __floats2half2_rn(v0, v1);
                __half2 h23 = __floats2half2_rn(v2, v3);
                *(__half2*)(Cd + (size_t)lr0 * NSP + lc)       = h01;
                *(__half2*)(Cd + (size_t)(lr0 + 8) * NSP + lc) = h23;
            } else {
                float* Cd = g_proj + ((size_t)bz * CCH + (size_t)mt * 128) * NSP + (size_t)nt * 128;
                *(float2*)(Cd + (size_t)lr0 * NSP + lc)       = make_float2(v0, v1);
                *(float2*)(Cd + (size_t)(lr0 + 8) * NSP + lc) = make_float2(v2, v3);
            }
        }
    }
}

// ---------------- kv partials + k rowsum partials (fp16 inputs) ----------------
__global__ void __launch_bounds__(256) kv_kernel() {
    int bh = blockIdx.x;
    int split = blockIdx.y;
    int b = bh >> 3, h = bh & 7;

    __shared__ float ks[32][132];
    __shared__ float vs[32][132];

    const __half* kbase = g_qkvh + ((size_t)b * MQKV + 256 + h * HD) * NSP + (size_t)split * 512;
    const __half* vbase = g_qkvh + ((size_t)b * MQKV + 512 + h * HD) * NSP + (size_t)split * 512;

    int t = threadIdx.x;
    int d0 = (t >> 4) << 1;
    int e0 = (t & 15) << 1;

    float a00 = 0.f, a01 = 0.f, a10 = 0.f, a11 = 0.f;
    float s0 = 0.f, s1 = 0.f;

    for (int ch = 0; ch < 4; ch++) {
        __syncthreads();
        #pragma unroll
        for (int it = 0; it < 2; it++) {
            int f = t + it * 256;
            int dr = f >> 4, dc = (f & 15) * 8;
            uint4 kr = *(const uint4*)(kbase + (size_t)dr * NSP + ch * 128 + dc);
            uint4 vr = *(const uint4*)(vbase + (size_t)dr * NSP + ch * 128 + dc);
            const __half2* kh = (const __half2*)&kr;
            const __half2* vh = (const __half2*)&vr;
            #pragma unroll
            for (int j = 0; j < 4; j++) {
                float2 kf = __half22float2(kh[j]);
                float2 vf = __half22float2(vh[j]);
                ks[dr][dc + 2*j    ] = kf.x;
                ks[dr][dc + 2*j + 1] = kf.y;
                vs[dr][dc + 2*j    ] = vf.x;
                vs[dr][dc + 2*j + 1] = vf.y;
            }
        }
        __syncthreads();
        #pragma unroll 4
        for (int n = 0; n < 128; n++) {
            float k0v = ks[d0][n],     k1v = ks[d0 + 1][n];
            float v0v = vs[e0][n],     v1v = vs[e0 + 1][n];
            a00 = fmaf(k0v, v0v, a00); a01 = fmaf(k0v, v1v, a01);
            a10 = fmaf(k1v, v0v, a10); a11 = fmaf(k1v, v1v, a11);
            s0 += k0v; s1 += k1v;
        }
    }

    float* dst = g_kvpart + ((size_t)split * 16 + bh) * 1024;
    dst[(d0    ) * 32 + e0    ] = a00;
    dst[(d0    ) * 32 + e0 + 1] = a01;
    dst[(d0 + 1) * 32 + e0    ] = a10;
    dst[(d0 + 1) * 32 + e0 + 1] = a11;
    if (e0 == 0) {
        g_ksump[(split * 16 + bh) * 32 + d0]     = s0;
        g_ksump[(split * 16 + bh) * 32 + d0 + 1] = s1;
    }
}

__global__ void kvreduce_kernel() {
    int i = blockIdx.x * 256 + threadIdx.x;
    if (i >= 16 * 1024) return;
    int bh = i >> 10, de = i & 1023;
    int d = de >> 5, e = de & 31;
    float rs = 0.f;
    #pragma unroll 8
    for (int sp = 0; sp < KVSPLIT; sp++)
        rs += g_ksump[(sp * 16 + bh) * 32 + d];
    float cs = fmaxf(rs, 1e-6f);
    float inv = 1.0f / cs;
    float s = 0.f;
    #pragma unroll 8
    for (int sp = 0; sp < KVSPLIT; sp++)
        s += g_kvpart[((size_t)sp * 16 + bh) * 1024 + de];
    g_kv[i] = s * inv;
    if (e == 0) {
        int b = bh >> 3, h = bh & 7;
        g_ksumA[b * CCH + h * HD + d] = rs * inv;
    }
}

// ---------------- out = kv^T·q / clip(normalizer) -> g_outh fp16 ----------
__global__ void __launch_bounds__(256) attnout_kernel() {
    int nblk = blockIdx.x;
    int bh = blockIdx.y;
    int b = bh >> 3, h = bh & 7;

    __shared__ float qs[32][132];
    __shared__ float kvs[32][32];
    __shared__ float ksA[32];

    int t = threadIdx.x;
    const __half* qbase = g_qkvh + ((size_t)b * MQKV + h * HD) * NSP + (size_t)nblk * 128;
    __half* obase = g_outh + ((size_t)b * CCH + h * HD) * NSP + (size_t)nblk * 128;

    #pragma unroll
    for (int it = 0; it < 2; it++) {
        int f = t + it * 256;
        int dr = f >> 4, dc = (f & 15) * 8;
        uint4 qr = *(const uint4*)(qbase + (size_t)dr * NSP + dc);
        const __half2* qh = (const __half2*)&qr;
        #pragma unroll
        for (int j = 0; j < 4; j++) {
            float2 qf = __half22float2(qh[j]);
            qs[dr][dc + 2*j    ] = qf.x;
            qs[dr][dc + 2*j + 1] = qf.y;
        }
    }
    #pragma unroll
    for (int it = 0; it < 4; it++)
        ((float*)kvs)[t + it * 256] = g_kv[bh * 1024 + t + it * 256];
    if (t < 32) ksA[t] = g_ksumA[b * CCH + h * HD + t];
    __syncthreads();

    int n  = t & 127;
    int e0 = (t >> 7) << 4;

    float norm = 0.f;
    #pragma unroll
    for (int d = 0; d < 32; d++) norm = fmaf(qs[d][n], ksA[d], norm);
    float rn = 1.0f / fmaxf(norm, 1e-6f);

    float acc[16];
    #pragma unroll
    for (int e = 0; e < 16; e++) acc[e] = 0.f;
    #pragma unroll
    for (int d = 0; d < 32; d++) {
        float qd = qs[d][n];
        #pragma unroll
        for (int e = 0; e < 16; e++)
            acc[e] = fmaf(qd, kvs[d][e0 + e], acc[e]);
    }
    #pragma unroll
    for (int e = 0; e < 16; e++)
        obase[(size_t)(e0 + e) * NSP + n] = __float2half_rn(acc[e] * rn);
}

// ---------------- final: y = x + GN2(proj) ----------------
__global__ void final_kernel(const float* __restrict__ x,
                             const float* __restrict__ ow, const float* __restrict__ ob,
                             float* __restrict__ out) {
    const int n4 = NSP / 4;
    const int total = BATCH * CCH * n4;
    for (int i = blockIdx.x * blockDim.x + threadIdx.x; i < total; i += gridDim.x * blockDim.x) {
        int row = i / n4;
        int c = row % CCH, b = row / CCH;
        int g = c / CPG;
        float mu = g_mu2[b * GRP + g], r = g_rstd2[b * GRP + g];
        float sc = r * ow[c];
        float sh = ob[c] - mu * sc;
        float4 xv = ((const float4*)x)[i];
        float4 pv = ((const float4*)g_proj)[i];
        float4 o;
        o.x = xv.x + fmaf(pv.x, sc, sh);
        o.y = xv.y + fmaf(pv.y, sc, sh);
        o.z = xv.z + fmaf(pv.z, sc, sh);
        o.w = xv.w + fmaf(pv.w, sc, sh);
        ((float4*)out)[i] = o;
    }
}

// ---------------- launch ----------------
extern "C" void kernel_launch(void* const* d_in, const int* in_sizes, int n_in,
                              void* d_out, int out_size) {
    const float* x      = (const float*)d_in[0];
    const float* norm_w = (const float*)d_in[1];
    const float* norm_b = (const float*)d_in[2];
    const float* qkv_w  = (const float*)d_in[3];
    const float* qkv_b  = (const float*)d_in[4];
    const float* out_w  = (const float*)d_in[5];
    const float* out_b  = (const float*)d_in[6];
    const float* onw    = (const float*)d_in[7];
    const float* onb    = (const float*)d_in[8];
    float* out = (float*)d_out;

    gn_stats_kernel<0><<<BATCH * GRP, 256>>>(x);
    prep_kernel<<<2, 256>>>(norm_w, norm_b);
    prep2_kernel<<<dim3(MQKV, BATCH), 256>>>(qkv_w, qkv_b);
    prep_ow_kernel<<<256, 256>>>(out_w);
    mma_gemm_kernel<0><<<dim3(NSP / 128, MQKV / 128, BATCH), 256>>>(nullptr);
    kv_kernel<<<dim3(16, KVSPLIT), 256>>>();
    kvreduce_kernel<<<64, 256>>>();
    attnout_kernel<<<dim3(NSP / 128, 16), 256>>>();
    mma_gemm_kernel<1><<<dim3(NSP / 128, CCH / 128, BATCH), 256>>>(out_b);
    gn_stats_kernel<1><<<BATCH * GRP, 256>>>(x /*unused*/);
    final_kernel<<<4096, 256>>>(x, onw, onb, out);
}

// round 7
// speedup vs baseline: 1.5283x; 1.1294x over previous
#include <cuda_runtime.h>
#include <cuda_fp16.h>
#include <cstdint>

// ---------------- problem constants ----------------
#define BATCH 2
#define CCH   256
#define NSP   32768
#define NHEAD 8
#define HD    32
#define GRP   32
#define CPG   8
#define MQKV  768
#define EPS   1e-5f
#define KVSPLIT 64

// ---------------- static scratch ----------------
__device__ __half g_qkvh[(size_t)BATCH * MQKV * NSP];   // fp16 q|k|v
__device__ __half g_xh[(size_t)BATCH * CCH * NSP];      // fp16 x
__device__ __half g_outh[(size_t)BATCH * CCH * NSP];    // fp16 attn out
__device__ float  g_proj[(size_t)BATCH * CCH * NSP];    // fp32 proj
__device__ __half g_a2h[(size_t)BATCH * MQKV * CCH];    // folded A' fp16
__device__ __half g_owh[CCH * CCH];                     // out_w fp16
__device__ float g_mu1[BATCH * GRP];
__device__ float g_rstd1[BATCH * GRP];
__device__ float g_mu2[BATCH * GRP];
__device__ float g_rstd2[BATCH * GRP];
__device__ float g_bias2[BATCH * MQKV];
__device__ float g_ksumA[BATCH * CCH];
__device__ float g_kvpart[(size_t)KVSPLIT * 16 * 1024];
__device__ float g_ksump[KVSPLIT * 16 * 32];
__device__ float g_kv[BATCH * NHEAD * HD * HD];
__device__ float g_gnpart[(size_t)BATCH * 256 * 64];    // per-(b,nt) GN2 partials (32 grp x {s,s2})

// ---------------- helpers ----------------
__device__ __forceinline__ float warp_sum(float v) {
    #pragma unroll
    for (int o = 16; o; o >>= 1) v += __shfl_xor_sync(0xffffffffu, v, o);
    return v;
}
__device__ __forceinline__ uint32_t smem_u32(const void* p) {
    uint32_t a;
    asm("{ .reg .u64 t; cvta.to.shared.u64 t, %1; cvt.u32.u64 %0, t; }" : "=r"(a) : "l"(p));
    return a;
}
__device__ __forceinline__ void cp16(uint32_t saddr, const void* g) {
    asm volatile("cp.async.cg.shared.global [%0], [%1], 16;" :: "r"(saddr), "l"(g) : "memory");
}
__device__ __forceinline__ void cp_commit() {
    asm volatile("cp.async.commit_group;" ::: "memory");
}
__device__ __forceinline__ void cp_wait1() {
    asm volatile("cp.async.wait_group 1;" ::: "memory");
}
__device__ __forceinline__ void ldm_x4(uint32_t* r, uint32_t addr) {
    asm volatile("ldmatrix.sync.aligned.m8n8.x4.shared.b16 {%0,%1,%2,%3}, [%4];"
        : "=r"(r[0]), "=r"(r[1]), "=r"(r[2]), "=r"(r[3]) : "r"(addr));
}
__device__ __forceinline__ void ldm_x4_trans(uint32_t* r, uint32_t addr) {
    asm volatile("ldmatrix.sync.aligned.m8n8.x4.trans.shared.b16 {%0,%1,%2,%3}, [%4];"
        : "=r"(r[0]), "=r"(r[1]), "=r"(r[2]), "=r"(r[3]) : "r"(addr));
}
__device__ __forceinline__ void mma_fp16(float* c, const uint32_t* a, uint32_t b0, uint32_t b1) {
    asm volatile(
        "mma.sync.aligned.m16n8k16.row.col.f32.f16.f16.f32 "
        "{%0,%1,%2,%3}, {%4,%5,%6,%7}, {%8,%9}, {%0,%1,%2,%3};"
        : "+f"(c[0]), "+f"(c[1]), "+f"(c[2]), "+f"(c[3])
        : "r"(a[0]), "r"(a[1]), "r"(a[2]), "r"(a[3]), "r"(b0), "r"(b1));
}

// ---------------- group-norm stats over x (also emits x as fp16) ----------------
__global__ void gn_stats0_kernel(const float* __restrict__ xsrc) {
    int grp = blockIdx.x;
    const float4* base = (const float4*)(xsrc + (size_t)grp * CPG * NSP);
    uint2* xh4 = (uint2*)(g_xh + (size_t)grp * CPG * NSP);
    const int M4 = CPG * NSP / 4;
    float s = 0.f, s2 = 0.f;
    for (int i = threadIdx.x; i < M4; i += 256) {
        float4 v = base[i];
        s  += (v.x + v.y) + (v.z + v.w);
        s2 += v.x * v.x + v.y * v.y + v.z * v.z + v.w * v.w;
        __half2 h0 = __floats2half2_rn(v.x, v.y);
        __half2 h1 = __floats2half2_rn(v.z, v.w);
        uint2 u;
        u.x = *(uint32_t*)&h0;
        u.y = *(uint32_t*)&h1;
        xh4[i] = u;
    }
    __shared__ float sh[8], sh2[8];
    s = warp_sum(s); s2 = warp_sum(s2);
    int w = threadIdx.x >> 5, l = threadIdx.x & 31;
    if (l == 0) { sh[w] = s; sh2[w] = s2; }
    __syncthreads();
    if (w == 0) {
        s  = (l < 8) ? sh[l]  : 0.f;
        s2 = (l < 8) ? sh2[l] : 0.f;
        s = warp_sum(s); s2 = warp_sum(s2);
        if (l == 0) {
            const float inv = 1.0f / (float)(CPG * NSP);
            float mu  = s * inv;
            float var = s2 * inv - mu * mu;
            g_mu1[grp] = mu;
            g_rstd1[grp] = rsqrtf(var + EPS);
        }
    }
}

// fold GN1 affine into weights: A' = fp16(W*sc), bias' = W@sh + qkv_b
__global__ void prep2_kernel(const float* __restrict__ qkv_w, const float* __restrict__ qkv_b,
                             const float* __restrict__ nw, const float* __restrict__ nb) {
    int o = blockIdx.x, b = blockIdx.y;
    int c = threadIdx.x;
    float mu = g_mu1[b * GRP + c / CPG];
    float r  = g_rstd1[b * GRP + c / CPG];
    float sc = r * nw[c];
    float sh = nb[c] - mu * sc;
    float w  = qkv_w[o * CCH + c];
    g_a2h[((size_t)b * MQKV + o) * CCH + c] = __float2half_rn(w * sc);
    float v = w * sh;
    __shared__ float red[8];
    v = warp_sum(v);
    int wp = c >> 5, l = c & 31;
    if (l == 0) red[wp] = v;
    __syncthreads();
    if (c == 0) {
        float s = 0.f;
        #pragma unroll
        for (int i = 0; i < 8; i++) s += red[i];
        g_bias2[b * MQKV + o] = s + qkv_b[o];
    }
}

__global__ void prep_ow_kernel(const float* __restrict__ out_w) {
    int i = blockIdx.x * 256 + threadIdx.x;
    if (i < CCH * CCH) g_owh[i] = __float2half_rn(out_w[i]);
}

// ======== fp16 GEMM: block-resident B (256x128), m-loop, depth-2 A pipeline ========
// MODE 0: A=g_a2h[bz] (768 rows, 6 m-tiles), B=g_xh, C=g_qkvh fp16 (elu rows<512)
// MODE 1: A=g_owh (256 rows, 2 m-tiles),     B=g_outh, C=g_proj fp32 + GN2 partials
#define ABUF 8192
#define BFULL 65536
#define GSMEM (3 * ABUF + BFULL)    // 90112 bytes

template<int MODE>
__global__ void __launch_bounds__(256, 2) mma_gemm_kernel(const float* __restrict__ bias_arg)
{
    extern __shared__ char smem[];
    const uint32_t sbase = smem_u32(smem);
    const uint32_t bOffB = 3u * ABUF;
    const int MT = (MODE == 0) ? 6 : 2;
    const int NG = MT * 8;

    __shared__ float gnacc[2][64];

    const int bz = blockIdx.z;
    const int nt = blockIdx.x;
    const int t  = threadIdx.x;
    const int warp = t >> 5, lane = t & 31;
    const int wm = warp >> 1;        // 0..3 : rows wm*32 within 128-row m-tile
    const int wn = warp & 1;         // 0..1 : cols wn*64
    const int g  = lane >> 2;
    const int c  = lane & 3;

    const __half* Ab0;
    const __half* Bb;
    const float* bias;
    if (MODE == 0) {
        Ab0  = g_a2h + (size_t)bz * MQKV * CCH;
        bias = g_bias2 + bz * MQKV;
        Bb   = g_xh + (size_t)bz * CCH * NSP + (size_t)nt * 128;
    } else {
        Ab0  = g_owh;
        bias = bias_arg;
        Bb   = g_outh + (size_t)bz * CCH * NSP + (size_t)nt * 128;
    }

    if (MODE == 1 && t < 128) gnacc[t >> 6][t & 63] = 0.f;

    // ---- B full panel load: 256 k-rows x 128 n (fp16), swizzled ----
    #pragma unroll
    for (int i = 0; i < 16; i++) {
        int f = t + i * 256;
        int k = f >> 4, cc = f & 15;
        cp16(sbase + bOffB + (uint32_t)(k * 256 + ((cc ^ (k & 7)) << 4)),
             Bb + (size_t)k * NSP + cc * 8);
    }
    cp_commit();

    // ---- A chunk loader: global chunk id Gc = mt2*8 + ch, buffer Gc%3 ----
    auto load_A = [&](int Gc) {
        int mt2 = Gc >> 3, ch = Gc & 7, buf = Gc - (Gc / 3) * 3;
        const __half* At = Ab0 + (size_t)mt2 * 128 * CCH;
        #pragma unroll
        for (int i = 0; i < 2; i++) {
            int f = t + i * 256;
            int m = f >> 2, k8 = f & 3;
            cp16(sbase + (uint32_t)buf * ABUF + (uint32_t)(m * 64 + ((k8 ^ ((m >> 1) & 3)) << 4)),
                 At + (size_t)m * CCH + ch * 32 + k8 * 8);
        }
        cp_commit();
    };
    load_A(0);
    load_A(1);

    // ldmatrix lane address bases
    uint32_t aAddrF[2];
    {
        int row_lo = (lane & 7) + ((lane >> 3) & 1) * 8;
        int kc = lane >> 4;
        #pragma unroll
        for (int i2 = 0; i2 < 2; i2++) {
            int row = wm * 32 + i2 * 16 + row_lo;
            aAddrF[i2] = (uint32_t)(row * 64 + ((kc ^ ((row >> 1) & 3)) << 4));
        }
    }
    uint32_t bAddrF;
    {
        int k  = (lane & 7) + ((lane >> 4) << 3);     // 0..15
        int nb = wn * 64 + ((lane >> 3) & 1) * 8;
        int cc = nb >> 3;
        bAddrF = (uint32_t)(k * 256 + ((cc ^ (k & 7)) << 4));
    }

    float acc[2][8][4];
    #pragma unroll
    for (int i = 0; i < 2; i++)
        #pragma unroll
        for (int j = 0; j < 8; j++)
            #pragma unroll
            for (int q = 0; q < 4; q++) acc[i][j][q] = 0.f;

    #pragma unroll 1
    for (int G = 0; G < NG; G++) {
        int kt = G & 7;
        int mt2 = G >> 3;
        int buf = G - (G / 3) * 3;

        cp_wait1();
        __syncthreads();
        if (G + 2 < NG) load_A(G + 2);
        else            cp_commit();         // empty group keeps wait_group 1 correct

        uint32_t aB = sbase + (uint32_t)buf * ABUF;
        uint32_t bB = sbase + bOffB + (uint32_t)kt * 8192;
        #pragma unroll
        for (int kg = 0; kg < 2; kg++) {
            uint32_t afr[2][4];
            #pragma unroll
            for (int i2 = 0; i2 < 2; i2++)
                ldm_x4(afr[i2], aB + (aAddrF[i2] ^ (kg << 5)));
            uint32_t bfr[4][4];
            #pragma unroll
            for (int j4 = 0; j4 < 4; j4++)
                ldm_x4_trans(bfr[j4], bB + ((bAddrF ^ (j4 << 5)) + (kg << 12)));
            #pragma unroll
            for (int j2 = 0; j2 < 8; j2++) {
                uint32_t b0 = bfr[j2 >> 1][(j2 & 1)];
                uint32_t b1 = bfr[j2 >> 1][(j2 & 1) + 2];
                #pragma unroll
                for (int i2 = 0; i2 < 2; i2++)
                    mma_fp16(acc[i2][j2], afr[i2], b0, b1);
            }
        }

        if (kt == 7) {
            // -------- epilogue for m-tile mt2 --------
            #pragma unroll
            for (int i2 = 0; i2 < 2; i2++) {
                int lr0 = wm * 32 + i2 * 16 + g;
                int o0  = mt2 * 128 + lr0;
                int o1  = o0 + 8;
                float bi0 = bias[o0], bi1 = bias[o1];
                float slo = 0.f, slo2 = 0.f, shi = 0.f, shi2 = 0.f;
                #pragma unroll
                for (int j2 = 0; j2 < 8; j2++) {
                    int lc = wn * 64 + j2 * 8 + 2 * c;
                    float v0 = acc[i2][j2][0] + bi0;
                    float v1 = acc[i2][j2][1] + bi0;
                    float v2 = acc[i2][j2][2] + bi1;
                    float v3 = acc[i2][j2][3] + bi1;
                    if (MODE == 0) {
                        if (o0 < 512) {
                            v0 = (v0 > 0.f) ? (v0 + 1.f) : __expf(v0);
                            v1 = (v1 > 0.f) ? (v1 + 1.f) : __expf(v1);
                        }
                        if (o1 < 512) {
                            v2 = (v2 > 0.f) ? (v2 + 1.f) : __expf(v2);
                            v3 = (v3 > 0.f) ? (v3 + 1.f) : __expf(v3);
                        }
                        __half* Cd = g_qkvh + ((size_t)bz * MQKV + (size_t)mt2 * 128) * NSP
                                   + (size_t)nt * 128;
                        *(__half2*)(Cd + (size_t)lr0 * NSP + lc)       = __floats2half2_rn(v0, v1);
                        *(__half2*)(Cd + (size_t)(lr0 + 8) * NSP + lc) = __floats2half2_rn(v2, v3);
                    } else {
                        float* Cd = g_proj + ((size_t)bz * CCH + (size_t)mt2 * 128) * NSP
                                  + (size_t)nt * 128;
                        *(float2*)(Cd + (size_t)lr0 * NSP + lc)       = make_float2(v0, v1);
                        *(float2*)(Cd + (size_t)(lr0 + 8) * NSP + lc) = make_float2(v2, v3);
                        slo += v0 + v1;  slo2 += v0 * v0 + v1 * v1;
                        shi += v2 + v3;  shi2 += v2 * v2 + v3 * v3;
                    }
                    #pragma unroll
                    for (int q = 0; q < 4; q++) acc[i2][j2][q] = 0.f;
                }
                if (MODE == 1) {
                    slo = warp_sum(slo);  slo2 = warp_sum(slo2);
                    shi = warp_sum(shi);  shi2 = warp_sum(shi2);
                    if (lane == 0) {
                        int Gi = mt2 * 16 + wm * 4 + i2 * 2;
                        gnacc[wn][Gi * 2]           += slo;
                        gnacc[wn][Gi * 2 + 1]       += slo2;
                        gnacc[wn][(Gi + 1) * 2]     += shi;
                        gnacc[wn][(Gi + 1) * 2 + 1] += shi2;
                    }
                }
            }
        }
    }

    if (MODE == 1) {
        __syncthreads();
        if (t < 64)
            g_gnpart[((size_t)bz * 256 + nt) * 64 + t] = gnacc[0][t] + gnacc[1][t];
    }
}

// ---------------- GN2 finalize: reduce 256 nt partials per (b, group) ----------------
__global__ void gn_finalize_kernel() {
    int bg = blockIdx.x;              // 0..63 = b*GRP+g
    int b = bg >> 5, gg = bg & 31;
    int t = threadIdx.x;              // 256
    float s  = g_gnpart[((size_t)b * 256 + t) * 64 + gg * 2];
    float s2 = g_gnpart[((size_t)b * 256 + t) * 64 + gg * 2 + 1];
    __shared__ float sh[8], sh2[8];
    s = warp_sum(s); s2 = warp_sum(s2);
    int w = t >> 5, l = t & 31;
    if (l == 0) { sh[w] = s; sh2[w] = s2; }
    __syncthreads();
    if (w == 0) {
        s  = (l < 8) ? sh[l]  : 0.f;
        s2 = (l < 8) ? sh2[l] : 0.f;
        s = warp_sum(s); s2 = warp_sum(s2);
        if (l == 0) {
            const float inv = 1.0f / (float)(CPG * NSP);
            float mu  = s * inv;
            float var = s2 * inv - mu * mu;
            g_mu2[bg] = mu;
            g_rstd2[bg] = rsqrtf(var + EPS);
        }
    }
}

// ---------------- kv partials + k rowsum partials (fp16 inputs) ----------------
__global__ void __launch_bounds__(256) kv_kernel() {
    int bh = blockIdx.x;
    int split = blockIdx.y;
    int b = bh >> 3, h = bh & 7;

    __shared__ float ks[32][132];
    __shared__ float vs[32][132];

    const __half* kbase = g_qkvh + ((size_t)b * MQKV + 256 + h * HD) * NSP + (size_t)split * 512;
    const __half* vbase = g_qkvh + ((size_t)b * MQKV + 512 + h * HD) * NSP + (size_t)split * 512;

    int t = threadIdx.x;
    int d0 = (t >> 4) << 1;
    int e0 = (t & 15) << 1;

    float a00 = 0.f, a01 = 0.f, a10 = 0.f, a11 = 0.f;
    float s0 = 0.f, s1 = 0.f;

    for (int ch = 0; ch < 4; ch++) {
        __syncthreads();
        #pragma unroll
        for (int it = 0; it < 2; it++) {
            int f = t + it * 256;
            int dr = f >> 4, dc = (f & 15) * 8;
            uint4 kr = *(const uint4*)(kbase + (size_t)dr * NSP + ch * 128 + dc);
            uint4 vr = *(const uint4*)(vbase + (size_t)dr * NSP + ch * 128 + dc);
            const __half2* kh = (const __half2*)&kr;
            const __half2* vh = (const __half2*)&vr;
            #pragma unroll
            for (int j = 0; j < 4; j++) {
                float2 kf = __half22float2(kh[j]);
                float2 vf = __half22float2(vh[j]);
                ks[dr][dc + 2*j    ] = kf.x;
                ks[dr][dc + 2*j + 1] = kf.y;
                vs[dr][dc + 2*j    ] = vf.x;
                vs[dr][dc + 2*j + 1] = vf.y;
            }
        }
        __syncthreads();
        #pragma unroll 4
        for (int n = 0; n < 128; n++) {
            float k0v = ks[d0][n],     k1v = ks[d0 + 1][n];
            float v0v = vs[e0][n],     v1v = vs[e0 + 1][n];
            a00 = fmaf(k0v, v0v, a00); a01 = fmaf(k0v, v1v, a01);
            a10 = fmaf(k1v, v0v, a10); a11 = fmaf(k1v, v1v, a11);
            s0 += k0v; s1 += k1v;
        }
    }

    float* dst = g_kvpart + ((size_t)split * 16 + bh) * 1024;
    dst[(d0    ) * 32 + e0    ] = a00;
    dst[(d0    ) * 32 + e0 + 1] = a01;
    dst[(d0 + 1) * 32 + e0    ] = a10;
    dst[(d0 + 1) * 32 + e0 + 1] = a11;
    if (e0 == 0) {
        g_ksump[(split * 16 + bh) * 32 + d0]     = s0;
        g_ksump[(split * 16 + bh) * 32 + d0 + 1] = s1;
    }
}

__global__ void kvreduce_kernel() {
    int i = blockIdx.x * 256 + threadIdx.x;
    if (i >= 16 * 1024) return;
    int bh = i >> 10, de = i & 1023;
    int d = de >> 5, e = de & 31;
    float rs = 0.f;
    #pragma unroll 8
    for (int sp = 0; sp < KVSPLIT; sp++)
        rs += g_ksump[(sp * 16 + bh) * 32 + d];
    float cs = fmaxf(rs, 1e-6f);
    float inv = 1.0f / cs;
    float s = 0.f;
    #pragma unroll 8
    for (int sp = 0; sp < KVSPLIT; sp++)
        s += g_kvpart[((size_t)sp * 16 + bh) * 1024 + de];
    g_kv[i] = s * inv;
    if (e == 0) {
        int b = bh >> 3, h = bh & 7;
        g_ksumA[b * CCH + h * HD + d] = rs * inv;
    }
}

// ---------------- out = kv^T·q / clip(normalizer) -> g_outh fp16 ----------
__global__ void __launch_bounds__(256) attnout_kernel() {
    int nblk = blockIdx.x;
    int bh = blockIdx.y;
    int b = bh >> 3, h = bh & 7;

    __shared__ float qs[32][132];
    __shared__ float kvs[32][32];
    __shared__ float ksA[32];

    int t = threadIdx.x;
    const __half* qbase = g_qkvh + ((size_t)b * MQKV + h * HD) * NSP + (size_t)nblk * 128;
    __half* obase = g_outh + ((size_t)b * CCH + h * HD) * NSP + (size_t)nblk * 128;

    #pragma unroll
    for (int it = 0; it < 2; it++) {
        int f = t + it * 256;
        int dr = f >> 4, dc = (f & 15) * 8;
        uint4 qr = *(const uint4*)(qbase + (size_t)dr * NSP + dc);
        const __half2* qh = (const __half2*)&qr;
        #pragma unroll
        for (int j = 0; j < 4; j++) {
            float2 qf = __half22float2(qh[j]);
            qs[dr][dc + 2*j    ] = qf.x;
            qs[dr][dc + 2*j + 1] = qf.y;
        }
    }
    #pragma unroll
    for (int it = 0; it < 4; it++)
        ((float*)kvs)[t + it * 256] = g_kv[bh * 1024 + t + it * 256];
    if (t < 32) ksA[t] = g_ksumA[b * CCH + h * HD + t];
    __syncthreads();

    int n  = t & 127;
    int e0 = (t >> 7) << 4;

    float norm = 0.f;
    #pragma unroll
    for (int d = 0; d < 32; d++) norm = fmaf(qs[d][n], ksA[d], norm);
    float rn = 1.0f / fmaxf(norm, 1e-6f);

    float acc[16];
    #pragma unroll
    for (int e = 0; e < 16; e++) acc[e] = 0.f;
    #pragma unroll
    for (int d = 0; d < 32; d++) {
        float qd = qs[d][n];
        #pragma unroll
        for (int e = 0; e < 16; e++)
            acc[e] = fmaf(qd, kvs[d][e0 + e], acc[e]);
    }
    #pragma unroll
    for (int e = 0; e < 16; e++)
        obase[(size_t)(e0 + e) * NSP + n] = __float2half_rn(acc[e] * rn);
}

// ---------------- final: y = x + GN2(proj) ----------------
__global__ void final_kernel(const float* __restrict__ x,
                             const float* __restrict__ ow, const float* __restrict__ ob,
                             float* __restrict__ out) {
    const int n4 = NSP / 4;
    const int total = BATCH * CCH * n4;
    for (int i = blockIdx.x * blockDim.x + threadIdx.x; i < total; i += gridDim.x * blockDim.x) {
        int row = i / n4;
        int c = row % CCH, b = row / CCH;
        int g = c / CPG;
        float mu = g_mu2[b * GRP + g], r = g_rstd2[b * GRP + g];
        float sc = r * ow[c];
        float sh = ob[c] - mu * sc;
        float4 xv = ((const float4*)x)[i];
        float4 pv = ((const float4*)g_proj)[i];
        float4 o;
        o.x = xv.x + fmaf(pv.x, sc, sh);
        o.y = xv.y + fmaf(pv.y, sc, sh);
        o.z = xv.z + fmaf(pv.z, sc, sh);
        o.w = xv.w + fmaf(pv.w, sc, sh);
        ((float4*)out)[i] = o;
    }
}

// ---------------- launch ----------------
extern "C" void kernel_launch(void* const* d_in, const int* in_sizes, int n_in,
                              void* d_out, int out_size) {
    const float* x      = (const float*)d_in[0];
    const float* norm_w = (const float*)d_in[1];
    const float* norm_b = (const float*)d_in[2];
    const float* qkv_w  = (const float*)d_in[3];
    const float* qkv_b  = (const float*)d_in[4];
    const float* out_w  = (const float*)d_in[5];
    const float* out_b  = (const float*)d_in[6];
    const float* onw    = (const float*)d_in[7];
    const float* onb    = (const float*)d_in[8];
    float* out = (float*)d_out;

    cudaFuncSetAttribute(mma_gemm_kernel<0>, cudaFuncAttributeMaxDynamicSharedMemorySize, GSMEM);
    cudaFuncSetAttribute(mma_gemm_kernel<1>, cudaFuncAttributeMaxDynamicSharedMemorySize, GSMEM);

    gn_stats0_kernel<<<BATCH * GRP, 256>>>(x);
    prep2_kernel<<<dim3(MQKV, BATCH), 256>>>(qkv_w, qkv_b, norm_w, norm_b);
    prep_ow_kernel<<<256, 256>>>(out_w);
    mma_gemm_kernel<0><<<dim3(256, 1, BATCH), 256, GSMEM>>>(nullptr);
    kv_kernel<<<dim3(16, KVSPLIT), 256>>>();
    kvreduce_kernel<<<64, 256>>>();
    attnout_kernel<<<dim3(256, 16), 256>>>();
    mma_gemm_kernel<1><<<dim3(256, 1, BATCH), 256, GSMEM>>>(out_b);
    gn_finalize_kernel<<<64, 256>>>();
    final_kernel<<<4096, 256>>>(x, onw, onb, out);
}

// round 9
// speedup vs baseline: 1.9635x; 1.2847x over previous
#include <cuda_runtime.h>
#include <cuda_fp16.h>
#include <cstdint>

// ---------------- problem constants ----------------
#define BATCH 2
#define CCH   256
#define NHEAD 8
#define HD    32
#define GRP   32
#define CPG   8
#define MQKV  768
#define NSP   32768
#define EPS   1e-5f
#define KVS   128      // kv splits, 256 seq cols each

// ---------------- static scratch ----------------
__device__ __half g_qkvh[(size_t)BATCH * MQKV * NSP];   // fp16 q|k|v
__device__ __half g_xh[(size_t)BATCH * CCH * NSP];      // fp16 x
__device__ __half g_qsc[(size_t)BATCH * CCH * NSP];     // fp16 q' = q/norm
__device__ __half g_projh[(size_t)BATCH * CCH * NSP];   // fp16 proj
__device__ __half g_a2h[(size_t)BATCH * MQKV * CCH];    // folded A' fp16
__device__ __half g_w2h[(size_t)BATCH * CCH * CCH];     // W2 = ow @ blockdiag(kv)^T fp16
__device__ float g_mu1[BATCH * GRP];
__device__ float g_rstd1[BATCH * GRP];
__device__ float g_mu2[BATCH * GRP];
__device__ float g_rstd2[BATCH * GRP];
__device__ float g_bias2[BATCH * MQKV];
__device__ float g_ksumA[BATCH * CCH];
__device__ float g_kvpart[(size_t)KVS * 16 * 1024];
__device__ float g_ksump[KVS * 16 * 32];
__device__ float g_kv[BATCH * NHEAD * HD * HD];
__device__ float g_gnpart[(size_t)BATCH * 256 * 64];

// ---------------- helpers ----------------
__device__ __forceinline__ float warp_sum(float v) {
    #pragma unroll
    for (int o = 16; o; o >>= 1) v += __shfl_xor_sync(0xffffffffu, v, o);
    return v;
}
__device__ __forceinline__ uint32_t smem_u32(const void* p) {
    uint32_t a;
    asm("{ .reg .u64 t; cvta.to.shared.u64 t, %1; cvt.u32.u64 %0, t; }" : "=r"(a) : "l"(p));
    return a;
}
__device__ __forceinline__ void cp16(uint32_t saddr, const void* g) {
    asm volatile("cp.async.cg.shared.global [%0], [%1], 16;" :: "r"(saddr), "l"(g) : "memory");
}
__device__ __forceinline__ void cp_commit() {
    asm volatile("cp.async.commit_group;" ::: "memory");
}
__device__ __forceinline__ void cp_wait1() {
    asm volatile("cp.async.wait_group 1;" ::: "memory");
}
__device__ __forceinline__ void ldm_x4(uint32_t* r, uint32_t addr) {
    asm volatile("ldmatrix.sync.aligned.m8n8.x4.shared.b16 {%0,%1,%2,%3}, [%4];"
        : "=r"(r[0]), "=r"(r[1]), "=r"(r[2]), "=r"(r[3]) : "r"(addr));
}
__device__ __forceinline__ void ldm_x4_trans(uint32_t* r, uint32_t addr) {
    asm volatile("ldmatrix.sync.aligned.m8n8.x4.trans.shared.b16 {%0,%1,%2,%3}, [%4];"
        : "=r"(r[0]), "=r"(r[1]), "=r"(r[2]), "=r"(r[3]) : "r"(addr));
}
__device__ __forceinline__ void mma_fp16(float* c, const uint32_t* a, uint32_t b0, uint32_t b1) {
    asm volatile(
        "mma.sync.aligned.m16n8k16.row.col.f32.f16.f16.f32 "
        "{%0,%1,%2,%3}, {%4,%5,%6,%7}, {%8,%9}, {%0,%1,%2,%3};"
        : "+f"(c[0]), "+f"(c[1]), "+f"(c[2]), "+f"(c[3])
        : "r"(a[0]), "r"(a[1]), "r"(a[2]), "r"(a[3]), "r"(b0), "r"(b1));
}

// ---------------- group-norm stats over x (also emits x as fp16) ----------------
__global__ void gn_stats0_kernel(const float* __restrict__ xsrc) {
    int grp = blockIdx.x;
    const float4* base = (const float4*)(xsrc + (size_t)grp * CPG * NSP);
    uint2* xh4 = (uint2*)(g_xh + (size_t)grp * CPG * NSP);
    const int M4 = CPG * NSP / 4;
    float s = 0.f, s2 = 0.f;
    for (int i = threadIdx.x; i < M4; i += 256) {
        float4 v = base[i];
        s  += (v.x + v.y) + (v.z + v.w);
        s2 += v.x * v.x + v.y * v.y + v.z * v.z + v.w * v.w;
        __half2 h0 = __floats2half2_rn(v.x, v.y);
        __half2 h1 = __floats2half2_rn(v.z, v.w);
        uint2 u;
        u.x = *(uint32_t*)&h0;
        u.y = *(uint32_t*)&h1;
        xh4[i] = u;
    }
    __shared__ float sh[8], sh2[8];
    s = warp_sum(s); s2 = warp_sum(s2);
    int w = threadIdx.x >> 5, l = threadIdx.x & 31;
    if (l == 0) { sh[w] = s; sh2[w] = s2; }
    __syncthreads();
    if (w == 0) {
        s  = (l < 8) ? sh[l]  : 0.f;
        s2 = (l < 8) ? sh2[l] : 0.f;
        s = warp_sum(s); s2 = warp_sum(s2);
        if (l == 0) {
            const float inv = 1.0f / (float)(CPG * NSP);
            float mu  = s * inv;
            float var = s2 * inv - mu * mu;
            g_mu1[grp] = mu;
            g_rstd1[grp] = rsqrtf(var + EPS);
        }
    }
}

// fold GN1 affine into weights: A' = fp16(W*sc), bias' = W@sh + qkv_b
__global__ void prep2_kernel(const float* __restrict__ qkv_w, const float* __restrict__ qkv_b,
                             const float* __restrict__ nw, const float* __restrict__ nb) {
    int o = blockIdx.x, b = blockIdx.y;
    int c = threadIdx.x;
    float mu = g_mu1[b * GRP + c / CPG];
    float r  = g_rstd1[b * GRP + c / CPG];
    float sc = r * nw[c];
    float sh = nb[c] - mu * sc;
    float w  = qkv_w[o * CCH + c];
    g_a2h[((size_t)b * MQKV + o) * CCH + c] = __float2half_rn(w * sc);
    float v = w * sh;
    __shared__ float red[8];
    v = warp_sum(v);
    int wp = c >> 5, l = c & 31;
    if (l == 0) red[wp] = v;
    __syncthreads();
    if (c == 0) {
        float s = 0.f;
        #pragma unroll
        for (int i = 0; i < 8; i++) s += red[i];
        g_bias2[b * MQKV + o] = s + qkv_b[o];
    }
}

// ======== fp16 GEMM: block-resident B (256x128), m-loop, depth-2 A pipeline ========
// MODE 0: A=g_a2h[bz] (6 m-tiles), B=g_xh, C=g_qkvh fp16 (elu rows<512)
// MODE 1: A=g_w2h[bz] (2 m-tiles), B=g_qsc, C=g_projh fp16 + GN2 partials
#define ABUF 8192
#define BFULL 65536
#define GSMEM (3 * ABUF + BFULL)

template<int MODE>
__global__ void __launch_bounds__(256, 2) mma_gemm_kernel(const float* __restrict__ bias_arg)
{
    extern __shared__ char smem[];
    const uint32_t sbase = smem_u32(smem);
    const uint32_t bOffB = 3u * ABUF;
    const int MT = (MODE == 0) ? 6 : 2;
    const int NG = MT * 8;

    __shared__ float gnacc[2][64];

    const int bz = blockIdx.z;
    const int nt = blockIdx.x;
    const int t  = threadIdx.x;
    const int warp = t >> 5, lane = t & 31;
    const int wm = warp >> 1;
    const int wn = warp & 1;
    const int g  = lane >> 2;
    const int c  = lane & 3;

    const __half* Ab0;
    const __half* Bb;
    const float* bias;
    if (MODE == 0) {
        Ab0  = g_a2h + (size_t)bz * MQKV * CCH;
        bias = g_bias2 + bz * MQKV;
        Bb   = g_xh + (size_t)bz * CCH * NSP + (size_t)nt * 128;
    } else {
        Ab0  = g_w2h + (size_t)bz * CCH * CCH;
        bias = bias_arg;
        Bb   = g_qsc + (size_t)bz * CCH * NSP + (size_t)nt * 128;
    }

    if (MODE == 1 && t < 128) gnacc[t >> 6][t & 63] = 0.f;

    #pragma unroll
    for (int i = 0; i < 16; i++) {
        int f = t + i * 256;
        int k = f >> 4, cc = f & 15;
        cp16(sbase + bOffB + (uint32_t)(k * 256 + ((cc ^ (k & 7)) << 4)),
             Bb + (size_t)k * NSP + cc * 8);
    }
    cp_commit();

    auto load_A = [&](int Gc) {
        int mt2 = Gc >> 3, ch = Gc & 7, buf = Gc - (Gc / 3) * 3;
        const __half* At = Ab0 + (size_t)mt2 * 128 * CCH;
        #pragma unroll
        for (int i = 0; i < 2; i++) {
            int f = t + i * 256;
            int m = f >> 2, k8 = f & 3;
            cp16(sbase + (uint32_t)buf * ABUF + (uint32_t)(m * 64 + ((k8 ^ ((m >> 1) & 3)) << 4)),
                 At + (size_t)m * CCH + ch * 32 + k8 * 8);
        }
        cp_commit();
    };
    load_A(0);
    load_A(1);

    uint32_t aAddrF[2];
    {
        int row_lo = (lane & 7) + ((lane >> 3) & 1) * 8;
        int kc = lane >> 4;
        #pragma unroll
        for (int i2 = 0; i2 < 2; i2++) {
            int row = wm * 32 + i2 * 16 + row_lo;
            aAddrF[i2] = (uint32_t)(row * 64 + ((kc ^ ((row >> 1) & 3)) << 4));
        }
    }
    uint32_t bAddrF;
    {
        int k  = (lane & 7) + ((lane >> 4) << 3);
        int nb = wn * 64 + ((lane >> 3) & 1) * 8;
        int cc = nb >> 3;
        bAddrF = (uint32_t)(k * 256 + ((cc ^ (k & 7)) << 4));
    }

    float acc[2][8][4];
    #pragma unroll
    for (int i = 0; i < 2; i++)
        #pragma unroll
        for (int j = 0; j < 8; j++)
            #pragma unroll
            for (int q = 0; q < 4; q++) acc[i][j][q] = 0.f;

    #pragma unroll 1
    for (int G = 0; G < NG; G++) {
        int kt = G & 7;
        int mt2 = G >> 3;
        int buf = G - (G / 3) * 3;

        cp_wait1();
        __syncthreads();
        if (G + 2 < NG) load_A(G + 2);
        else            cp_commit();

        uint32_t aB = sbase + (uint32_t)buf * ABUF;
        uint32_t bB = sbase + bOffB + (uint32_t)kt * 8192;
        #pragma unroll
        for (int kg = 0; kg < 2; kg++) {
            uint32_t afr[2][4];
            #pragma unroll
            for (int i2 = 0; i2 < 2; i2++)
                ldm_x4(afr[i2], aB + (aAddrF[i2] ^ (kg << 5)));
            uint32_t bfr[4][4];
            #pragma unroll
            for (int j4 = 0; j4 < 4; j4++)
                ldm_x4_trans(bfr[j4], bB + ((bAddrF ^ (j4 << 5)) + (kg << 12)));
            #pragma unroll
            for (int j2 = 0; j2 < 8; j2++) {
                uint32_t b0 = bfr[j2 >> 1][(j2 & 1)];
                uint32_t b1 = bfr[j2 >> 1][(j2 & 1) + 2];
                #pragma unroll
                for (int i2 = 0; i2 < 2; i2++)
                    mma_fp16(acc[i2][j2], afr[i2], b0, b1);
            }
        }

        if (kt == 7) {
            #pragma unroll
            for (int i2 = 0; i2 < 2; i2++) {
                int lr0 = wm * 32 + i2 * 16 + g;
                int o0  = mt2 * 128 + lr0;
                int o1  = o0 + 8;
                float bi0 = bias[o0], bi1 = bias[o1];
                float slo = 0.f, slo2 = 0.f, shi = 0.f, shi2 = 0.f;
                #pragma unroll
                for (int j2 = 0; j2 < 8; j2++) {
                    int lc = wn * 64 + j2 * 8 + 2 * c;
                    float v0 = acc[i2][j2][0] + bi0;
                    float v1 = acc[i2][j2][1] + bi0;
                    float v2 = acc[i2][j2][2] + bi1;
                    float v3 = acc[i2][j2][3] + bi1;
                    if (MODE == 0) {
                        if (o0 < 512) {
                            v0 = (v0 > 0.f) ? (v0 + 1.f) : __expf(v0);
                            v1 = (v1 > 0.f) ? (v1 + 1.f) : __expf(v1);
                        }
                        if (o1 < 512) {
                            v2 = (v2 > 0.f) ? (v2 + 1.f) : __expf(v2);
                            v3 = (v3 > 0.f) ? (v3 + 1.f) : __expf(v3);
                        }
                        __half* Cd = g_qkvh + ((size_t)bz * MQKV + (size_t)mt2 * 128) * NSP
                                   + (size_t)nt * 128;
                        *(__half2*)(Cd + (size_t)lr0 * NSP + lc)       = __floats2half2_rn(v0, v1);
                        *(__half2*)(Cd + (size_t)(lr0 + 8) * NSP + lc) = __floats2half2_rn(v2, v3);
                    } else {
                        __half* Cd = g_projh + ((size_t)bz * CCH + (size_t)mt2 * 128) * NSP
                                   + (size_t)nt * 128;
                        *(__half2*)(Cd + (size_t)lr0 * NSP + lc)       = __floats2half2_rn(v0, v1);
                        *(__half2*)(Cd + (size_t)(lr0 + 8) * NSP + lc) = __floats2half2_rn(v2, v3);
                        slo += v0 + v1;  slo2 += v0 * v0 + v1 * v1;
                        shi += v2 + v3;  shi2 += v2 * v2 + v3 * v3;
                    }
                    #pragma unroll
                    for (int q = 0; q < 4; q++) acc[i2][j2][q] = 0.f;
                }
                if (MODE == 1) {
                    slo = warp_sum(slo);  slo2 = warp_sum(slo2);
                    shi = warp_sum(shi);  shi2 = warp_sum(shi2);
                    if (lane == 0) {
                        int Gi = mt2 * 16 + wm * 4 + i2 * 2;
                        gnacc[wn][Gi * 2]           += slo;
                        gnacc[wn][Gi * 2 + 1]       += slo2;
                        gnacc[wn][(Gi + 1) * 2]     += shi;
                        gnacc[wn][(Gi + 1) * 2 + 1] += shi2;
                    }
                }
            }
        }
    }

    if (MODE == 1) {
        __syncthreads();
        if (t < 64)
            g_gnpart[((size_t)bz * 256 + nt) * 64 + t] = gnacc[0][t] + gnacc[1][t];
    }
}

// ---------------- kv = k·v^T via tensor cores, fused k rowsums ----------------
// grid (16 bh, 128 splits of 256 seq cols), 256 thr = 8 warps, warp K-slice 32.
__global__ void __launch_bounds__(256) kv_mma_kernel() {
    int bh = blockIdx.x, split = blockIdx.y;
    int b = bh >> 3, h = bh & 7;

    __shared__ __align__(16) char sm[33792];
    __half* ks = (__half*)sm;                 // 32 rows x 264 halves (528B stride)
    __half* vs = (__half*)(sm + 16896);
    float*  red = (float*)sm;                 // reused after frags consumed

    const int t = threadIdx.x;
    const int lane = t & 31, w = t >> 5;
    const int g = lane >> 2, c = lane & 3;

    const __half* kbase = g_qkvh + ((size_t)b * MQKV + 256 + h * HD) * NSP + (size_t)split * 256;
    const __half* vbase = g_qkvh + ((size_t)b * MQKV + 512 + h * HD) * NSP + (size_t)split * 256;

    // FIX (R8 bug): full tile is 32 rows x 256 halves = 1024 uint4 per tensor.
    #pragma unroll
    for (int i = 0; i < 4; i++) {
        int f = t + i * 256;
        int r = f >> 5, c32 = f & 31;
        *(uint4*)(ks + r * 264 + c32 * 8) = *(const uint4*)(kbase + (size_t)r * NSP + c32 * 8);
        *(uint4*)(vs + r * 264 + c32 * 8) = *(const uint4*)(vbase + (size_t)r * NSP + c32 * 8);
    }
    __syncthreads();

    // k rowsum partials: thread t sums 32 cols of row t>>3
    {
        int r = t >> 3, seg = t & 7;
        float s = 0.f;
        #pragma unroll
        for (int j = 0; j < 16; j++) {
            float2 kf = __half22float2(*(const __half2*)(ks + r * 264 + seg * 32 + 2 * j));
            s += kf.x + kf.y;
        }
        #pragma unroll
        for (int o = 4; o; o >>= 1) s += __shfl_xor_sync(0xffffffffu, s, o);
        if (seg == 0) g_ksump[(split * 16 + bh) * 32 + r] = s;
    }

    // fragments (A = k rows d, B = v rows e; both stored [row][seq] row-major)
    int row_lo = (lane & 7) + ((lane >> 3) & 1) * 8;
    int ksel = lane >> 4;
    uint32_t kbyte = (uint32_t)(w * 64 + ksel * 16);

    float acc[2][4][4];
    #pragma unroll
    for (int i = 0; i < 2; i++)
        #pragma unroll
        for (int j = 0; j < 4; j++)
            #pragma unroll
            for (int q = 0; q < 4; q++) acc[i][j][q] = 0.f;

    uint32_t ksb = smem_u32(ks), vsb = smem_u32(vs);
    #pragma unroll
    for (int kg = 0; kg < 2; kg++) {
        uint32_t afr[2][4], bfr[2][4];
        #pragma unroll
        for (int i2 = 0; i2 < 2; i2++)
            ldm_x4(afr[i2], ksb + (uint32_t)((i2 * 16 + row_lo) * 528) + kbyte + kg * 32);
        #pragma unroll
        for (int j4 = 0; j4 < 2; j4++)
            ldm_x4(bfr[j4], vsb + (uint32_t)((j4 * 16 + row_lo) * 528) + kbyte + kg * 32);
        #pragma unroll
        for (int j = 0; j < 4; j++) {
            uint32_t b0 = bfr[j >> 1][(j & 1)];
            uint32_t b1 = bfr[j >> 1][(j & 1) + 2];
            #pragma unroll
            for (int i2 = 0; i2 < 2; i2++)
                mma_fp16(acc[i2][j], afr[i2], b0, b1);
        }
    }
    __syncthreads();          // all ks/vs reads done -> reuse as reduction buffer

    #pragma unroll
    for (int i2 = 0; i2 < 2; i2++)
        #pragma unroll
        for (int j = 0; j < 4; j++) {
            int r0 = i2 * 16 + g, cc = j * 8 + 2 * c;
            red[w * 1024 + r0 * 32 + cc]           = acc[i2][j][0];
            red[w * 1024 + r0 * 32 + cc + 1]       = acc[i2][j][1];
            red[w * 1024 + (r0 + 8) * 32 + cc]     = acc[i2][j][2];
            red[w * 1024 + (r0 + 8) * 32 + cc + 1] = acc[i2][j][3];
        }
    __syncthreads();

    #pragma unroll
    for (int u = 0; u < 4; u++) {
        int de = t * 4 + u;
        float s = 0.f;
        #pragma unroll
        for (int ww = 0; ww < 8; ww++) s += red[ww * 1024 + de];
        g_kvpart[((size_t)split * 16 + bh) * 1024 + de] = s;
    }
}

// reduce kv partials + rowsums; apply 1/clip; emit ksumA
__global__ void kvreduce_kernel() {
    int i = blockIdx.x * 256 + threadIdx.x;
    if (i >= 16 * 1024) return;
    int bh = i >> 10, de = i & 1023;
    int d = de >> 5, e = de & 31;
    float rs = 0.f;
    #pragma unroll 8
    for (int sp = 0; sp < KVS; sp++)
        rs += g_ksump[(sp * 16 + bh) * 32 + d];
    float cs = fmaxf(rs, 1e-6f);
    float inv = 1.0f / cs;
    float s = 0.f;
    #pragma unroll 8
    for (int sp = 0; sp < KVS; sp++)
        s += g_kvpart[((size_t)sp * 16 + bh) * 1024 + de];
    g_kv[i] = s * inv;
    if (e == 0) {
        int b = bh >> 3, h = bh & 7;
        g_ksumA[b * CCH + h * HD + d] = rs * inv;
    }
}

// ---------------- q' = q / clip(norm) ----------------
__global__ void __launch_bounds__(256) qscale_kernel() {
    int nblk = blockIdx.x;
    int bh = blockIdx.y;
    int b = bh >> 3, h = bh & 7;

    __shared__ float qs[32][132];
    __shared__ float ksA[32];

    int t = threadIdx.x;
    const __half* qbase = g_qkvh + ((size_t)b * MQKV + h * HD) * NSP + (size_t)nblk * 128;
    __half* obase = g_qsc + ((size_t)b * CCH + h * HD) * NSP + (size_t)nblk * 128;

    #pragma unroll
    for (int it = 0; it < 2; it++) {
        int f = t + it * 256;
        int dr = f >> 4, dc = (f & 15) * 8;
        uint4 qr = *(const uint4*)(qbase + (size_t)dr * NSP + dc);
        const __half2* qh = (const __half2*)&qr;
        #pragma unroll
        for (int j = 0; j < 4; j++) {
            float2 qf = __half22float2(qh[j]);
            qs[dr][dc + 2*j    ] = qf.x;
            qs[dr][dc + 2*j + 1] = qf.y;
        }
    }
    if (t < 32) ksA[t] = g_ksumA[b * CCH + h * HD + t];
    __syncthreads();

    int n  = t & 127;
    int d0 = (t >> 7) << 4;   // rows 0-15 or 16-31

    float norm = 0.f;
    #pragma unroll
    for (int d = 0; d < 32; d++) norm = fmaf(qs[d][n], ksA[d], norm);
    float rn = 1.0f / fmaxf(norm, 1e-6f);

    #pragma unroll
    for (int d = 0; d < 16; d++)
        obase[(size_t)(d0 + d) * NSP + n] = __float2half_rn(qs[d0 + d][n] * rn);
}

// ---------------- W2 = ow @ blockdiag(kv)^T (per batch) ----------------
__global__ void w2prep_kernel(const float* __restrict__ out_w) {
    int o = blockIdx.x, b = blockIdx.y;
    int t = threadIdx.x;            // t = h*32+d
    __shared__ float owrow[256];
    owrow[t] = out_w[o * CCH + t];
    __syncthreads();
    int h = t >> 5, d = t & 31;
    const float* kvp = g_kv + (b * 8 + h) * 1024 + d * 32;
    const float* owp = owrow + h * 32;
    float s = 0.f;
    #pragma unroll
    for (int e = 0; e < 32; e++) s = fmaf(owp[e], kvp[e], s);
    g_w2h[((size_t)b * CCH + o) * CCH + t] = __float2half_rn(s);
}

// ---------------- GN2 finalize ----------------
__global__ void gn_finalize_kernel() {
    int bg = blockIdx.x;
    int b = bg >> 5, gg = bg & 31;
    int t = threadIdx.x;
    float s  = g_gnpart[((size_t)b * 256 + t) * 64 + gg * 2];
    float s2 = g_gnpart[((size_t)b * 256 + t) * 64 + gg * 2 + 1];
    __shared__ float sh[8], sh2[8];
    s = warp_sum(s); s2 = warp_sum(s2);
    int w = t >> 5, l = t & 31;
    if (l == 0) { sh[w] = s; sh2[w] = s2; }
    __syncthreads();
    if (w == 0) {
        s  = (l < 8) ? sh[l]  : 0.f;
        s2 = (l < 8) ? sh2[l] : 0.f;
        s = warp_sum(s); s2 = warp_sum(s2);
        if (l == 0) {
            const float inv = 1.0f / (float)(CPG * NSP);
            float mu  = s * inv;
            float var = s2 * inv - mu * mu;
            g_mu2[bg] = mu;
            g_rstd2[bg] = rsqrtf(var + EPS);
        }
    }
}

// ---------------- final: y = x + GN2(proj) ----------------
__global__ void final_kernel(const float* __restrict__ x,
                             const float* __restrict__ ow, const float* __restrict__ ob,
                             float* __restrict__ out) {
    const int n4 = NSP / 4;
    const int total = BATCH * CCH * n4;
    const __half2* ph = (const __half2*)g_projh;
    for (int i = blockIdx.x * blockDim.x + threadIdx.x; i < total; i += gridDim.x * blockDim.x) {
        int row = i / n4;
        int c = row % CCH, b = row / CCH;
        int g = c / CPG;
        float mu = g_mu2[b * GRP + g], r = g_rstd2[b * GRP + g];
        float sc = r * ow[c];
        float sh = ob[c] - mu * sc;
        float4 xv = ((const float4*)x)[i];
        float2 p0 = __half22float2(ph[2 * i]);
        float2 p1 = __half22float2(ph[2 * i + 1]);
        float4 o;
        o.x = xv.x + fmaf(p0.x, sc, sh);
        o.y = xv.y + fmaf(p0.y, sc, sh);
        o.z = xv.z + fmaf(p1.x, sc, sh);
        o.w = xv.w + fmaf(p1.y, sc, sh);
        ((float4*)out)[i] = o;
    }
}

// ---------------- launch ----------------
extern "C" void kernel_launch(void* const* d_in, const int* in_sizes, int n_in,
                              void* d_out, int out_size) {
    const float* x      = (const float*)d_in[0];
    const float* norm_w = (const float*)d_in[1];
    const float* norm_b = (const float*)d_in[2];
    const float* qkv_w  = (const float*)d_in[3];
    const float* qkv_b  = (const float*)d_in[4];
    const float* out_w  = (const float*)d_in[5];
    const float* out_b  = (const float*)d_in[6];
    const float* onw    = (const float*)d_in[7];
    const float* onb    = (const float*)d_in[8];
    float* out = (float*)d_out;

    cudaFuncSetAttribute(mma_gemm_kernel<0>, cudaFuncAttributeMaxDynamicSharedMemorySize, GSMEM);
    cudaFuncSetAttribute(mma_gemm_kernel<1>, cudaFuncAttributeMaxDynamicSharedMemorySize, GSMEM);

    gn_stats0_kernel<<<BATCH * GRP, 256>>>(x);
    prep2_kernel<<<dim3(MQKV, BATCH), 256>>>(qkv_w, qkv_b, norm_w, norm_b);
    mma_gemm_kernel<0><<<dim3(256, 1, BATCH), 256, GSMEM>>>(nullptr);
    kv_mma_kernel<<<dim3(16, KVS), 256>>>();
    kvreduce_kernel<<<64, 256>>>();
    qscale_kernel<<<dim3(256, 16), 256>>>();
    w2prep_kernel<<<dim3(CCH, BATCH), 256>>>(out_w);
    mma_gemm_kernel<1><<<dim3(256, 1, BATCH), 256, GSMEM>>>(out_b);
    gn_finalize_kernel<<<64, 256>>>();
    final_kernel<<<4096, 256>>>(x, onw, onb, out);
}

// round 10
// speedup vs baseline: 2.1037x; 1.0714x over previous
#include <cuda_runtime.h>
#include <cuda_fp16.h>
#include <cstdint>

// ---------------- problem constants ----------------
#define BATCH 2
#define CCH   256
#define NHEAD 8
#define HD    32
#define GRP   32
#define CPG   8
#define MQKV  768
#define NSP   32768
#define EPS   1e-5f
#define KVS   32       // kv splits, 1024 seq cols each

// ---------------- static scratch ----------------
__device__ __half g_qkvh[(size_t)BATCH * MQKV * NSP];   // fp16 q|k|v
__device__ __half g_xh[(size_t)BATCH * CCH * NSP];      // fp16 x (raw)
__device__ __half g_projh[(size_t)BATCH * CCH * NSP];   // fp16 proj
__device__ __half g_a2h[(size_t)BATCH * MQKV * CCH];    // folded A' fp16
__device__ __half g_w2h[(size_t)BATCH * CCH * CCH];     // W2 = ow @ blockdiag(kv)^T fp16
__device__ float g_mu1[BATCH * GRP];
__device__ float g_rstd1[BATCH * GRP];
__device__ float g_mu2[BATCH * GRP];
__device__ float g_rstd2[BATCH * GRP];
__device__ float g_bias2[BATCH * MQKV];
__device__ float g_ksumA[BATCH * CCH];
__device__ float g_kvpart[(size_t)KVS * 16 * 1024];
__device__ float g_ksump[KVS * 16 * 32];
__device__ float g_kv[BATCH * NHEAD * HD * HD];
__device__ float g_gnpart[(size_t)BATCH * 256 * 64];

// ---------------- helpers ----------------
__device__ __forceinline__ float warp_sum(float v) {
    #pragma unroll
    for (int o = 16; o; o >>= 1) v += __shfl_xor_sync(0xffffffffu, v, o);
    return v;
}
__device__ __forceinline__ uint32_t smem_u32(const void* p) {
    uint32_t a;
    asm("{ .reg .u64 t; cvta.to.shared.u64 t, %1; cvt.u32.u64 %0, t; }" : "=r"(a) : "l"(p));
    return a;
}
__device__ __forceinline__ void cp16(uint32_t saddr, const void* g) {
    asm volatile("cp.async.cg.shared.global [%0], [%1], 16;" :: "r"(saddr), "l"(g) : "memory");
}
__device__ __forceinline__ void cp_commit() {
    asm volatile("cp.async.commit_group;" ::: "memory");
}
__device__ __forceinline__ void cp_wait1() {
    asm volatile("cp.async.wait_group 1;" ::: "memory");
}
__device__ __forceinline__ void ldm_x4(uint32_t* r, uint32_t addr) {
    asm volatile("ldmatrix.sync.aligned.m8n8.x4.shared.b16 {%0,%1,%2,%3}, [%4];"
        : "=r"(r[0]), "=r"(r[1]), "=r"(r[2]), "=r"(r[3]) : "r"(addr));
}
__device__ __forceinline__ void ldm_x4_trans(uint32_t* r, uint32_t addr) {
    asm volatile("ldmatrix.sync.aligned.m8n8.x4.trans.shared.b16 {%0,%1,%2,%3}, [%4];"
        : "=r"(r[0]), "=r"(r[1]), "=r"(r[2]), "=r"(r[3]) : "r"(addr));
}
__device__ __forceinline__ void mma_fp16(float* c, const uint32_t* a, uint32_t b0, uint32_t b1) {
    asm volatile(
        "mma.sync.aligned.m16n8k16.row.col.f32.f16.f16.f32 "
        "{%0,%1,%2,%3}, {%4,%5,%6,%7}, {%8,%9}, {%0,%1,%2,%3};"
        : "+f"(c[0]), "+f"(c[1]), "+f"(c[2]), "+f"(c[3])
        : "r"(a[0]), "r"(a[1]), "r"(a[2]), "r"(a[3]), "r"(b0), "r"(b1));
}

// ---------------- group-norm stats over x (also emits x as fp16) ----------------
__global__ void gn_stats0_kernel(const float* __restrict__ xsrc) {
    int grp = blockIdx.x;
    const float4* base = (const float4*)(xsrc + (size_t)grp * CPG * NSP);
    uint2* xh4 = (uint2*)(g_xh + (size_t)grp * CPG * NSP);
    const int M4 = CPG * NSP / 4;
    float s = 0.f, s2 = 0.f;
    for (int i = threadIdx.x; i < M4; i += 256) {
        float4 v = base[i];
        s  += (v.x + v.y) + (v.z + v.w);
        s2 += v.x * v.x + v.y * v.y + v.z * v.z + v.w * v.w;
        __half2 h0 = __floats2half2_rn(v.x, v.y);
        __half2 h1 = __floats2half2_rn(v.z, v.w);
        uint2 u;
        u.x = *(uint32_t*)&h0;
        u.y = *(uint32_t*)&h1;
        xh4[i] = u;
    }
    __shared__ float sh[8], sh2[8];
    s = warp_sum(s); s2 = warp_sum(s2);
    int w = threadIdx.x >> 5, l = threadIdx.x & 31;
    if (l == 0) { sh[w] = s; sh2[w] = s2; }
    __syncthreads();
    if (w == 0) {
        s  = (l < 8) ? sh[l]  : 0.f;
        s2 = (l < 8) ? sh2[l] : 0.f;
        s = warp_sum(s); s2 = warp_sum(s2);
        if (l == 0) {
            const float inv = 1.0f / (float)(CPG * NSP);
            float mu  = s * inv;
            float var = s2 * inv - mu * mu;
            g_mu1[grp] = mu;
            g_rstd1[grp] = rsqrtf(var + EPS);
        }
    }
}

// fold GN1 affine into weights: A' = fp16(W*sc), bias' = W@sh + qkv_b
__global__ void prep2_kernel(const float* __restrict__ qkv_w, const float* __restrict__ qkv_b,
                             const float* __restrict__ nw, const float* __restrict__ nb) {
    int o = blockIdx.x, b = blockIdx.y;
    int c = threadIdx.x;
    float mu = g_mu1[b * GRP + c / CPG];
    float r  = g_rstd1[b * GRP + c / CPG];
    float sc = r * nw[c];
    float sh = nb[c] - mu * sc;
    float w  = qkv_w[o * CCH + c];
    g_a2h[((size_t)b * MQKV + o) * CCH + c] = __float2half_rn(w * sc);
    float v = w * sh;
    __shared__ float red[8];
    v = warp_sum(v);
    int wp = c >> 5, l = c & 31;
    if (l == 0) red[wp] = v;
    __syncthreads();
    if (c == 0) {
        float s = 0.f;
        #pragma unroll
        for (int i = 0; i < 8; i++) s += red[i];
        g_bias2[b * MQKV + o] = s + qkv_b[o];
    }
}

// ======== fp16 GEMM: block-resident B (256x128), m-loop, depth-2 A pipeline ========
// MODE 0: A=g_a2h[bz] (6 m-tiles), B=g_xh, C=g_qkvh fp16 (elu rows<512)
// MODE 1: A=g_w2h[bz] (2 m-tiles), B=raw q (normalized in-smem), C=g_projh + GN2 partials
#define ABUF 8192
#define BFULL 65536
#define GSMEM (3 * ABUF + BFULL)

template<int MODE>
__global__ void __launch_bounds__(256, 2) mma_gemm_kernel(const float* __restrict__ bias_arg)
{
    extern __shared__ char smem[];
    const uint32_t sbase = smem_u32(smem);
    const uint32_t bOffB = 3u * ABUF;
    const int MT = (MODE == 0) ? 6 : 2;
    const int NG = MT * 8;

    __shared__ float gnacc[2][64];
    __shared__ float ksA_sm[256];
    __shared__ float normsm[1024];    // rn[h][n], 8 x 128

    const int bz = blockIdx.z;
    const int nt = blockIdx.x;
    const int t  = threadIdx.x;
    const int warp = t >> 5, lane = t & 31;
    const int wm = warp >> 1;
    const int wn = warp & 1;
    const int g  = lane >> 2;
    const int c  = lane & 3;

    const __half* Ab0;
    const __half* Bb;
    const float* bias;
    if (MODE == 0) {
        Ab0  = g_a2h + (size_t)bz * MQKV * CCH;
        bias = g_bias2 + bz * MQKV;
        Bb   = g_xh + (size_t)bz * CCH * NSP + (size_t)nt * 128;
    } else {
        Ab0  = g_w2h + (size_t)bz * CCH * CCH;
        bias = bias_arg;
        Bb   = g_qkvh + (size_t)bz * MQKV * NSP + (size_t)nt * 128;   // raw q rows 0..255
    }

    if (MODE == 1) {
        if (t < 128) gnacc[t >> 6][t & 63] = 0.f;
        ksA_sm[t] = g_ksumA[bz * CCH + t];
    }

    #pragma unroll
    for (int i = 0; i < 16; i++) {
        int f = t + i * 256;
        int k = f >> 4, cc = f & 15;
        cp16(sbase + bOffB + (uint32_t)(k * 256 + ((cc ^ (k & 7)) << 4)),
             Bb + (size_t)k * NSP + cc * 8);
    }
    cp_commit();

    auto load_A = [&](int Gc) {
        int mt2 = Gc >> 3, ch = Gc & 7, buf = Gc - (Gc / 3) * 3;
        const __half* At = Ab0 + (size_t)mt2 * 128 * CCH;
        #pragma unroll
        for (int i = 0; i < 2; i++) {
            int f = t + i * 256;
            int m = f >> 2, k8 = f & 3;
            cp16(sbase + (uint32_t)buf * ABUF + (uint32_t)(m * 64 + ((k8 ^ ((m >> 1) & 3)) << 4)),
                 At + (size_t)m * CCH + ch * 32 + k8 * 8);
        }
        cp_commit();
    };
    load_A(0);
    load_A(1);

    uint32_t aAddrF[2];
    {
        int row_lo = (lane & 7) + ((lane >> 3) & 1) * 8;
        int kc = lane >> 4;
        #pragma unroll
        for (int i2 = 0; i2 < 2; i2++) {
            int row = wm * 32 + i2 * 16 + row_lo;
            aAddrF[i2] = (uint32_t)(row * 64 + ((kc ^ ((row >> 1) & 3)) << 4));
        }
    }
    uint32_t bAddrF;
    {
        int k  = (lane & 7) + ((lane >> 4) << 3);
        int nb = wn * 64 + ((lane >> 3) & 1) * 8;
        int cc = nb >> 3;
        bAddrF = (uint32_t)(k * 256 + ((cc ^ (k & 7)) << 4));
    }

    float acc[2][8][4];
    #pragma unroll
    for (int i = 0; i < 2; i++)
        #pragma unroll
        for (int j = 0; j < 8; j++)
            #pragma unroll
            for (int q = 0; q < 4; q++) acc[i][j][q] = 0.f;

    #pragma unroll 1
    for (int G = 0; G < NG; G++) {
        int kt = G & 7;
        int mt2 = G >> 3;
        int buf = G - (G / 3) * 3;

        cp_wait1();
        __syncthreads();
        if (G + 2 < NG) load_A(G + 2);
        else            cp_commit();

        // ---- MODE 1, first iteration: normalize q panel in smem ----
        if (MODE == 1 && G == 0) {
            // norms: 1024 (h,n) pairs, 4 per thread
            #pragma unroll
            for (int u = 0; u < 4; u++) {
                int idx = u * 256 + t;
                int h = idx >> 7, n = idx & 127;
                int cc = n >> 3, off = (n & 7) * 2;
                float s = 0.f;
                #pragma unroll
                for (int d = 0; d < 32; d++) {
                    int r = h * 32 + d;
                    const __half* p = (const __half*)(smem + bOffB
                        + r * 256 + ((cc ^ (r & 7)) << 4) + off);
                    s = fmaf(__half2float(*p), ksA_sm[r], s);
                }
                normsm[idx] = 1.0f / fmaxf(s, 1e-6f);
            }
            __syncthreads();
            // scale panel in place: 16384 half2, 64 per thread
            #pragma unroll
            for (int u = 0; u < 64; u++) {
                int idx = u * 256 + t;
                int r = idx >> 6, n2 = idx & 63;
                int col0 = n2 * 2;
                int cc = col0 >> 3;
                __half2* p = (__half2*)(smem + bOffB
                    + r * 256 + ((cc ^ (r & 7)) << 4) + (col0 & 7) * 2);
                float2 v = __half22float2(*p);
                int h = r >> 5;
                v.x *= normsm[h * 128 + col0];
                v.y *= normsm[h * 128 + col0 + 1];
                *p = __floats2half2_rn(v.x, v.y);
            }
            __syncthreads();
        }

        uint32_t aB = sbase + (uint32_t)buf * ABUF;
        uint32_t bB = sbase + bOffB + (uint32_t)kt * 8192;
        #pragma unroll
        for (int kg = 0; kg < 2; kg++) {
            uint32_t afr[2][4];
            #pragma unroll
            for (int i2 = 0; i2 < 2; i2++)
                ldm_x4(afr[i2], aB + (aAddrF[i2] ^ (kg << 5)));
            uint32_t bfr[4][4];
            #pragma unroll
            for (int j4 = 0; j4 < 4; j4++)
                ldm_x4_trans(bfr[j4], bB + ((bAddrF ^ (j4 << 5)) + (kg << 12)));
            #pragma unroll
            for (int j2 = 0; j2 < 8; j2++) {
                uint32_t b0 = bfr[j2 >> 1][(j2 & 1)];
                uint32_t b1 = bfr[j2 >> 1][(j2 & 1) + 2];
                #pragma unroll
                for (int i2 = 0; i2 < 2; i2++)
                    mma_fp16(acc[i2][j2], afr[i2], b0, b1);
            }
        }

        if (kt == 7) {
            #pragma unroll
            for (int i2 = 0; i2 < 2; i2++) {
                int lr0 = wm * 32 + i2 * 16 + g;
                int o0  = mt2 * 128 + lr0;
                int o1  = o0 + 8;
                float bi0 = bias[o0], bi1 = bias[o1];
                float slo = 0.f, slo2 = 0.f, shi = 0.f, shi2 = 0.f;
                #pragma unroll
                for (int j2 = 0; j2 < 8; j2++) {
                    int lc = wn * 64 + j2 * 8 + 2 * c;
                    float v0 = acc[i2][j2][0] + bi0;
                    float v1 = acc[i2][j2][1] + bi0;
                    float v2 = acc[i2][j2][2] + bi1;
                    float v3 = acc[i2][j2][3] + bi1;
                    if (MODE == 0) {
                        if (o0 < 512) {
                            v0 = (v0 > 0.f) ? (v0 + 1.f) : __expf(v0);
                            v1 = (v1 > 0.f) ? (v1 + 1.f) : __expf(v1);
                        }
                        if (o1 < 512) {
                            v2 = (v2 > 0.f) ? (v2 + 1.f) : __expf(v2);
                            v3 = (v3 > 0.f) ? (v3 + 1.f) : __expf(v3);
                        }
                        __half* Cd = g_qkvh + ((size_t)bz * MQKV + (size_t)mt2 * 128) * NSP
                                   + (size_t)nt * 128;
                        *(__half2*)(Cd + (size_t)lr0 * NSP + lc)       = __floats2half2_rn(v0, v1);
                        *(__half2*)(Cd + (size_t)(lr0 + 8) * NSP + lc) = __floats2half2_rn(v2, v3);
                    } else {
                        __half* Cd = g_projh + ((size_t)bz * CCH + (size_t)mt2 * 128) * NSP
                                   + (size_t)nt * 128;
                        *(__half2*)(Cd + (size_t)lr0 * NSP + lc)       = __floats2half2_rn(v0, v1);
                        *(__half2*)(Cd + (size_t)(lr0 + 8) * NSP + lc) = __floats2half2_rn(v2, v3);
                        slo += v0 + v1;  slo2 += v0 * v0 + v1 * v1;
                        shi += v2 + v3;  shi2 += v2 * v2 + v3 * v3;
                    }
                    #pragma unroll
                    for (int q = 0; q < 4; q++) acc[i2][j2][q] = 0.f;
                }
                if (MODE == 1) {
                    slo = warp_sum(slo);  slo2 = warp_sum(slo2);
                    shi = warp_sum(shi);  shi2 = warp_sum(shi2);
                    if (lane == 0) {
                        int Gi = mt2 * 16 + wm * 4 + i2 * 2;
                        gnacc[wn][Gi * 2]           += slo;
                        gnacc[wn][Gi * 2 + 1]       += slo2;
                        gnacc[wn][(Gi + 1) * 2]     += shi;
                        gnacc[wn][(Gi + 1) * 2 + 1] += shi2;
                    }
                }
            }
        }
    }

    if (MODE == 1) {
        __syncthreads();
        if (t < 64)
            g_gnpart[((size_t)bz * 256 + nt) * 64 + t] = gnacc[0][t] + gnacc[1][t];
    }
}

// ---------------- kv = k·v^T via tensor cores, fused k rowsums ----------------
// grid (16 bh, 32 splits of 1024 seq cols), 256 thr = 8 warps. 4 inner slices of 256.
__global__ void __launch_bounds__(256) kv_mma_kernel() {
    int bh = blockIdx.x, split = blockIdx.y;
    int b = bh >> 3, h = bh & 7;

    __shared__ __align__(16) char sm[33792];
    __half* ks = (__half*)sm;                 // 32 rows x 264 halves (528B stride)
    __half* vs = (__half*)(sm + 16896);
    float*  red = (float*)sm;                 // reused after all slices done

    const int t = threadIdx.x;
    const int lane = t & 31, w = t >> 5;
    const int g = lane >> 2, c = lane & 3;

    const __half* kbase = g_qkvh + ((size_t)b * MQKV + 256 + h * HD) * NSP + (size_t)split * 1024;
    const __half* vbase = g_qkvh + ((size_t)b * MQKV + 512 + h * HD) * NSP + (size_t)split * 1024;

    int row_lo = (lane & 7) + ((lane >> 3) & 1) * 8;
    int ksel = lane >> 4;
    uint32_t kbyte = (uint32_t)(w * 64 + ksel * 16);
    uint32_t ksb = smem_u32(ks), vsb = smem_u32(vs);

    float acc[2][4][4];
    #pragma unroll
    for (int i = 0; i < 2; i++)
        #pragma unroll
        for (int j = 0; j < 4; j++)
            #pragma unroll
            for (int q = 0; q < 4; q++) acc[i][j][q] = 0.f;
    float rsum = 0.f;
    const int rr = t >> 3, seg = t & 7;

    #pragma unroll 1
    for (int sl = 0; sl < 4; sl++) {
        __syncthreads();
        #pragma unroll
        for (int i = 0; i < 4; i++) {
            int f = t + i * 256;
            int r = f >> 5, c32 = f & 31;
            *(uint4*)(ks + r * 264 + c32 * 8) =
                *(const uint4*)(kbase + (size_t)r * NSP + sl * 256 + c32 * 8);
            *(uint4*)(vs + r * 264 + c32 * 8) =
                *(const uint4*)(vbase + (size_t)r * NSP + sl * 256 + c32 * 8);
        }
        __syncthreads();

        // rowsum partial for row rr, columns seg*32..seg*32+31 (accumulated over slices)
        #pragma unroll
        for (int j = 0; j < 16; j++) {
            float2 kf = __half22float2(*(const __half2*)(ks + rr * 264 + seg * 32 + 2 * j));
            rsum += kf.x + kf.y;
        }

        #pragma unroll
        for (int kg = 0; kg < 2; kg++) {
            uint32_t afr[2][4], bfr[2][4];
            #pragma unroll
            for (int i2 = 0; i2 < 2; i2++)
                ldm_x4(afr[i2], ksb + (uint32_t)((i2 * 16 + row_lo) * 528) + kbyte + kg * 32);
            #pragma unroll
            for (int j4 = 0; j4 < 2; j4++)
                ldm_x4(bfr[j4], vsb + (uint32_t)((j4 * 16 + row_lo) * 528) + kbyte + kg * 32);
            #pragma unroll
            for (int j = 0; j < 4; j++) {
                uint32_t b0 = bfr[j >> 1][(j & 1)];
                uint32_t b1 = bfr[j >> 1][(j & 1) + 2];
                #pragma unroll
                for (int i2 = 0; i2 < 2; i2++)
                    mma_fp16(acc[i2][j], afr[i2], b0, b1);
            }
        }
    }

    // rowsum reduce (8 segs per row)
    {
        float s = rsum;
        #pragma unroll
        for (int o = 4; o; o >>= 1) s += __shfl_xor_sync(0xffffffffu, s, o);
        if (seg == 0) g_ksump[(split * 16 + bh) * 32 + rr] = s;
    }
    __syncthreads();          // all ks/vs reads done -> reuse as reduction buffer

    #pragma unroll
    for (int i2 = 0; i2 < 2; i2++)
        #pragma unroll
        for (int j = 0; j < 4; j++) {
            int r0 = i2 * 16 + g, cc = j * 8 + 2 * c;
            red[w * 1024 + r0 * 32 + cc]           = acc[i2][j][0];
            red[w * 1024 + r0 * 32 + cc + 1]       = acc[i2][j][1];
            red[w * 1024 + (r0 + 8) * 32 + cc]     = acc[i2][j][2];
            red[w * 1024 + (r0 + 8) * 32 + cc + 1] = acc[i2][j][3];
        }
    __syncthreads();

    #pragma unroll
    for (int u = 0; u < 4; u++) {
        int de = t * 4 + u;
        float s = 0.f;
        #pragma unroll
        for (int ww = 0; ww < 8; ww++) s += red[ww * 1024 + de];
        g_kvpart[((size_t)split * 16 + bh) * 1024 + de] = s;
    }
}

// reduce kv partials + rowsums; apply 1/clip; emit ksumA
__global__ void kvreduce_kernel() {
    int i = blockIdx.x * 256 + threadIdx.x;
    if (i >= 16 * 1024) return;
    int bh = i >> 10, de = i & 1023;
    int d = de >> 5, e = de & 31;
    float rs = 0.f;
    #pragma unroll 8
    for (int sp = 0; sp < KVS; sp++)
        rs += g_ksump[(sp * 16 + bh) * 32 + d];
    float cs = fmaxf(rs, 1e-6f);
    float inv = 1.0f / cs;
    float s = 0.f;
    #pragma unroll 8
    for (int sp = 0; sp < KVS; sp++)
        s += g_kvpart[((size_t)sp * 16 + bh) * 1024 + de];
    g_kv[i] = s * inv;
    if (e == 0) {
        int b = bh >> 3, h = bh & 7;
        g_ksumA[b * CCH + h * HD + d] = rs * inv;
    }
}

// ---------------- W2 = ow @ blockdiag(kv)^T (per batch) ----------------
__global__ void w2prep_kernel(const float* __restrict__ out_w) {
    int o = blockIdx.x, b = blockIdx.y;
    int t = threadIdx.x;            // t = h*32+d
    __shared__ float owrow[256];
    owrow[t] = out_w[o * CCH + t];
    __syncthreads();
    int h = t >> 5, d = t & 31;
    const float* kvp = g_kv + (b * 8 + h) * 1024 + d * 32;
    const float* owp = owrow + h * 32;
    float s = 0.f;
    #pragma unroll
    for (int e = 0; e < 32; e++) s = fmaf(owp[e], kvp[e], s);
    g_w2h[((size_t)b * CCH + o) * CCH + t] = __float2half_rn(s);
}

// ---------------- GN2 finalize ----------------
__global__ void gn_finalize_kernel() {
    int bg = blockIdx.x;
    int b = bg >> 5, gg = bg & 31;
    int t = threadIdx.x;
    float s  = g_gnpart[((size_t)b * 256 + t) * 64 + gg * 2];
    float s2 = g_gnpart[((size_t)b * 256 + t) * 64 + gg * 2 + 1];
    __shared__ float sh[8], sh2[8];
    s = warp_sum(s); s2 = warp_sum(s2);
    int w = t >> 5, l = t & 31;
    if (l == 0) { sh[w] = s; sh2[w] = s2; }
    __syncthreads();
    if (w == 0) {
        s  = (l < 8) ? sh[l]  : 0.f;
        s2 = (l < 8) ? sh2[l] : 0.f;
        s = warp_sum(s); s2 = warp_sum(s2);
        if (l == 0) {
            const float inv = 1.0f / (float)(CPG * NSP);
            float mu  = s * inv;
            float var = s2 * inv - mu * mu;
            g_mu2[bg] = mu;
            g_rstd2[bg] = rsqrtf(var + EPS);
        }
    }
}

// ---------------- final: y = xh + GN2(proj) ----------------
__global__ void final_kernel(const float* __restrict__ ow, const float* __restrict__ ob,
                             float* __restrict__ out) {
    const int n4 = NSP / 4;
    const int total = BATCH * CCH * n4;
    const __half2* ph = (const __half2*)g_projh;
    const __half2* xh = (const __half2*)g_xh;
    for (int i = blockIdx.x * blockDim.x + threadIdx.x; i < total; i += gridDim.x * blockDim.x) {
        int row = i / n4;
        int c = row % CCH, b = row / CCH;
        int g = c / CPG;
        float mu = g_mu2[b * GRP + g], r = g_rstd2[b * GRP + g];
        float sc = r * ow[c];
        float sh = ob[c] - mu * sc;
        float2 x0 = __half22float2(xh[2 * i]);
        float2 x1 = __half22float2(xh[2 * i + 1]);
        float2 p0 = __half22float2(ph[2 * i]);
        float2 p1 = __half22float2(ph[2 * i + 1]);
        float4 o;
        o.x = x0.x + fmaf(p0.x, sc, sh);
        o.y = x0.y + fmaf(p0.y, sc, sh);
        o.z = x1.x + fmaf(p1.x, sc, sh);
        o.w = x1.y + fmaf(p1.y, sc, sh);
        ((float4*)out)[i] = o;
    }
}

// ---------------- launch ----------------
extern "C" void kernel_launch(void* const* d_in, const int* in_sizes, int n_in,
                              void* d_out, int out_size) {
    const float* x      = (const float*)d_in[0];
    const float* norm_w = (const float*)d_in[1];
    const float* norm_b = (const float*)d_in[2];
    const float* qkv_w  = (const float*)d_in[3];
    const float* qkv_b  = (const float*)d_in[4];
    const float* out_w  = (const float*)d_in[5];
    const float* out_b  = (const float*)d_in[6];
    const float* onw    = (const float*)d_in[7];
    const float* onb    = (const float*)d_in[8];
    float* out = (float*)d_out;

    cudaFuncSetAttribute(mma_gemm_kernel<0>, cudaFuncAttributeMaxDynamicSharedMemorySize, GSMEM);
    cudaFuncSetAttribute(mma_gemm_kernel<1>, cudaFuncAttributeMaxDynamicSharedMemorySize, GSMEM);

    gn_stats0_kernel<<<BATCH * GRP, 256>>>(x);
    prep2_kernel<<<dim3(MQKV, BATCH), 256>>>(qkv_w, qkv_b, norm_w, norm_b);
    mma_gemm_kernel<0><<<dim3(256, 1, BATCH), 256, GSMEM>>>(nullptr);
    kv_mma_kernel<<<dim3(16, KVS), 256>>>();
    kvreduce_kernel<<<64, 256>>>();
    w2prep_kernel<<<dim3(CCH, BATCH), 256>>>(out_w);
    mma_gemm_kernel<1><<<dim3(256, 1, BATCH), 256, GSMEM>>>(out_b);
    gn_finalize_kernel<<<64, 256>>>();
    final_kernel<<<4096, 256>>>(onw, onb, out);
}

// round 11
// speedup vs baseline: 2.1527x; 1.0233x over previous
#include <cuda_runtime.h>
#include <cuda_fp16.h>
#include <cstdint>

// ---------------- problem constants ----------------
#define BATCH 2
#define CCH   256
#define NHEAD 8
#define HD    32
#define GRP   32
#define CPG   8
#define MQKV  768
#define NSP   32768
#define EPS   1e-5f
#define KVS   32       // kv splits, 1024 seq cols each

// ---------------- static scratch ----------------
__device__ __half g_qkvh[(size_t)BATCH * MQKV * NSP];   // fp16 q|k|v
__device__ __half g_xh[(size_t)BATCH * CCH * NSP];      // fp16 x (raw)
__device__ __half g_projh[(size_t)BATCH * CCH * NSP];   // fp16 proj
__device__ __half g_a2h[(size_t)BATCH * MQKV * CCH];    // folded A' fp16
__device__ __half g_w2h[(size_t)BATCH * CCH * CCH];     // W2 fp16
__device__ float g_mu1[BATCH * GRP];
__device__ float g_rstd1[BATCH * GRP];
__device__ float g_mu2[BATCH * GRP];
__device__ float g_rstd2[BATCH * GRP];
__device__ float g_bias2[BATCH * MQKV];
__device__ float g_ksumA[BATCH * CCH];
__device__ float g_kvpart[(size_t)KVS * 16 * 1024];
__device__ float g_ksump[KVS * 16 * 32];
__device__ float g_kv[BATCH * NHEAD * HD * HD];
__device__ float g_gnpart[(size_t)BATCH * 256 * 64];

// ---------------- helpers ----------------
__device__ __forceinline__ float warp_sum(float v) {
    #pragma unroll
    for (int o = 16; o; o >>= 1) v += __shfl_xor_sync(0xffffffffu, v, o);
    return v;
}
__device__ __forceinline__ uint32_t smem_u32(const void* p) {
    uint32_t a;
    asm("{ .reg .u64 t; cvta.to.shared.u64 t, %1; cvt.u32.u64 %0, t; }" : "=r"(a) : "l"(p));
    return a;
}
__device__ __forceinline__ void cp16(uint32_t saddr, const void* g) {
    asm volatile("cp.async.cg.shared.global [%0], [%1], 16;" :: "r"(saddr), "l"(g) : "memory");
}
__device__ __forceinline__ void cp_commit() {
    asm volatile("cp.async.commit_group;" ::: "memory");
}
__device__ __forceinline__ void cp_wait1() {
    asm volatile("cp.async.wait_group 1;" ::: "memory");
}
__device__ __forceinline__ void ldm_x4(uint32_t* r, uint32_t addr) {
    asm volatile("ldmatrix.sync.aligned.m8n8.x4.shared.b16 {%0,%1,%2,%3}, [%4];"
        : "=r"(r[0]), "=r"(r[1]), "=r"(r[2]), "=r"(r[3]) : "r"(addr));
}
__device__ __forceinline__ void ldm_x4_trans(uint32_t* r, uint32_t addr) {
    asm volatile("ldmatrix.sync.aligned.m8n8.x4.trans.shared.b16 {%0,%1,%2,%3}, [%4];"
        : "=r"(r[0]), "=r"(r[1]), "=r"(r[2]), "=r"(r[3]) : "r"(addr));
}
__device__ __forceinline__ void mma_fp16(float* c, const uint32_t* a, uint32_t b0, uint32_t b1) {
    asm volatile(
        "mma.sync.aligned.m16n8k16.row.col.f32.f16.f16.f32 "
        "{%0,%1,%2,%3}, {%4,%5,%6,%7}, {%8,%9}, {%0,%1,%2,%3};"
        : "+f"(c[0]), "+f"(c[1]), "+f"(c[2]), "+f"(c[3])
        : "r"(a[0]), "r"(a[1]), "r"(a[2]), "r"(a[3]), "r"(b0), "r"(b1));
}

// ---------------- group-norm stats over x (also emits x as fp16) ----------------
__global__ void gn_stats0_kernel(const float* __restrict__ xsrc) {
    int grp = blockIdx.x;
    const float4* base = (const float4*)(xsrc + (size_t)grp * CPG * NSP);
    uint2* xh4 = (uint2*)(g_xh + (size_t)grp * CPG * NSP);
    const int M4 = CPG * NSP / 4;
    float s = 0.f, s2 = 0.f;
    for (int i = threadIdx.x; i < M4; i += 256) {
        float4 v = base[i];
        s  += (v.x + v.y) + (v.z + v.w);
        s2 += v.x * v.x + v.y * v.y + v.z * v.z + v.w * v.w;
        __half2 h0 = __floats2half2_rn(v.x, v.y);
        __half2 h1 = __floats2half2_rn(v.z, v.w);
        uint2 u;
        u.x = *(uint32_t*)&h0;
        u.y = *(uint32_t*)&h1;
        xh4[i] = u;
    }
    __shared__ float sh[8], sh2[8];
    s = warp_sum(s); s2 = warp_sum(s2);
    int w = threadIdx.x >> 5, l = threadIdx.x & 31;
    if (l == 0) { sh[w] = s; sh2[w] = s2; }
    __syncthreads();
    if (w == 0) {
        s  = (l < 8) ? sh[l]  : 0.f;
        s2 = (l < 8) ? sh2[l] : 0.f;
        s = warp_sum(s); s2 = warp_sum(s2);
        if (l == 0) {
            const float inv = 1.0f / (float)(CPG * NSP);
            float mu  = s * inv;
            float var = s2 * inv - mu * mu;
            g_mu1[grp] = mu;
            g_rstd1[grp] = rsqrtf(var + EPS);
        }
    }
}

// fold GN1 affine into weights: A' = fp16(W*sc), bias' = W@sh + qkv_b
__global__ void prep2_kernel(const float* __restrict__ qkv_w, const float* __restrict__ qkv_b,
                             const float* __restrict__ nw, const float* __restrict__ nb) {
    int o = blockIdx.x, b = blockIdx.y;
    int c = threadIdx.x;
    float mu = g_mu1[b * GRP + c / CPG];
    float r  = g_rstd1[b * GRP + c / CPG];
    float sc = r * nw[c];
    float sh = nb[c] - mu * sc;
    float w  = qkv_w[o * CCH + c];
    g_a2h[((size_t)b * MQKV + o) * CCH + c] = __float2half_rn(w * sc);
    float v = w * sh;
    __shared__ float red[8];
    v = warp_sum(v);
    int wp = c >> 5, l = c & 31;
    if (l == 0) red[wp] = v;
    __syncthreads();
    if (c == 0) {
        float s = 0.f;
        #pragma unroll
        for (int i = 0; i < 8; i++) s += red[i];
        g_bias2[b * MQKV + o] = s + qkv_b[o];
    }
}

// ======== fp16 GEMM: block-resident B (256x128), m-loop, depth-2 A pipeline ========
// MODE 0: A=g_a2h[bz] (6 m-tiles), B=g_xh, C=g_qkvh fp16 (elu rows<512)
// MODE 1: A=g_w2h[bz] (2 m-tiles), B=raw q (normalized in-smem), C=g_projh + GN2 partials
#define ABUF 8192
#define BFULL 65536
#define GSMEM (3 * ABUF + BFULL)

template<int MODE>
__global__ void __launch_bounds__(256, 2) mma_gemm_kernel(const float* __restrict__ bias_arg)
{
    extern __shared__ char smem[];
    const uint32_t sbase = smem_u32(smem);
    const uint32_t bOffB = 3u * ABUF;
    const int MT = (MODE == 0) ? 6 : 2;
    const int NG = MT * 8;

    __shared__ float gnacc[2][64];
    __shared__ float ksA_sm[256];
    __shared__ float normsm[1024];    // rn[h][n], 8 x 128

    const int bz = blockIdx.z;
    const int nt = blockIdx.x;
    const int t  = threadIdx.x;
    const int warp = t >> 5, lane = t & 31;
    const int wm = warp >> 1;
    const int wn = warp & 1;
    const int g  = lane >> 2;
    const int c  = lane & 3;

    const __half* Ab0;
    const __half* Bb;
    const float* bias;
    if (MODE == 0) {
        Ab0  = g_a2h + (size_t)bz * MQKV * CCH;
        bias = g_bias2 + bz * MQKV;
        Bb   = g_xh + (size_t)bz * CCH * NSP + (size_t)nt * 128;
    } else {
        Ab0  = g_w2h + (size_t)bz * CCH * CCH;
        bias = bias_arg;
        Bb   = g_qkvh + (size_t)bz * MQKV * NSP + (size_t)nt * 128;   // raw q rows 0..255
    }

    if (MODE == 1) {
        if (t < 128) gnacc[t >> 6][t & 63] = 0.f;
        ksA_sm[t] = g_ksumA[bz * CCH + t];
    }

    #pragma unroll
    for (int i = 0; i < 16; i++) {
        int f = t + i * 256;
        int k = f >> 4, cc = f & 15;
        cp16(sbase + bOffB + (uint32_t)(k * 256 + ((cc ^ (k & 7)) << 4)),
             Bb + (size_t)k * NSP + cc * 8);
    }
    cp_commit();

    auto load_A = [&](int Gc) {
        int mt2 = Gc >> 3, ch = Gc & 7, buf = Gc - (Gc / 3) * 3;
        const __half* At = Ab0 + (size_t)mt2 * 128 * CCH;
        #pragma unroll
        for (int i = 0; i < 2; i++) {
            int f = t + i * 256;
            int m = f >> 2, k8 = f & 3;
            cp16(sbase + (uint32_t)buf * ABUF + (uint32_t)(m * 64 + ((k8 ^ ((m >> 1) & 3)) << 4)),
                 At + (size_t)m * CCH + ch * 32 + k8 * 8);
        }
        cp_commit();
    };
    load_A(0);
    load_A(1);

    uint32_t aAddrF[2];
    {
        int row_lo = (lane & 7) + ((lane >> 3) & 1) * 8;
        int kc = lane >> 4;
        #pragma unroll
        for (int i2 = 0; i2 < 2; i2++) {
            int row = wm * 32 + i2 * 16 + row_lo;
            aAddrF[i2] = (uint32_t)(row * 64 + ((kc ^ ((row >> 1) & 3)) << 4));
        }
    }
    uint32_t bAddrF;
    {
        int k  = (lane & 7) + ((lane >> 4) << 3);
        int nb = wn * 64 + ((lane >> 3) & 1) * 8;
        int cc = nb >> 3;
        bAddrF = (uint32_t)(k * 256 + ((cc ^ (k & 7)) << 4));
    }

    float acc[2][8][4];
    #pragma unroll
    for (int i = 0; i < 2; i++)
        #pragma unroll
        for (int j = 0; j < 8; j++)
            #pragma unroll
            for (int q = 0; q < 4; q++) acc[i][j][q] = 0.f;

    #pragma unroll 1
    for (int G = 0; G < NG; G++) {
        int kt = G & 7;
        int mt2 = G >> 3;
        int buf = G - (G / 3) * 3;

        cp_wait1();
        __syncthreads();
        if (G + 2 < NG) load_A(G + 2);
        else            cp_commit();

        // ---- MODE 1, first iteration: normalize q panel in smem (half2 pairs) ----
        if (MODE == 1 && G == 0) {
            #pragma unroll
            for (int u = 0; u < 2; u++) {
                int idx = u * 256 + t;           // 0..511 : h*64 + n-pair
                int h = idx >> 6, n2 = idx & 63;
                int col0 = n2 * 2;
                int cc = col0 >> 3, off = (col0 & 7) * 2;
                float sx = 0.f, sy = 0.f;
                #pragma unroll
                for (int d = 0; d < 32; d++) {
                    int r = h * 32 + d;
                    const __half2* p = (const __half2*)(smem + bOffB
                        + r * 256 + ((cc ^ (r & 7)) << 4) + off);
                    float2 v = __half22float2(*p);
                    float ka = ksA_sm[r];
                    sx = fmaf(v.x, ka, sx);
                    sy = fmaf(v.y, ka, sy);
                }
                normsm[h * 128 + col0]     = 1.0f / fmaxf(sx, 1e-6f);
                normsm[h * 128 + col0 + 1] = 1.0f / fmaxf(sy, 1e-6f);
            }
            __syncthreads();
            // scale panel in place: 16384 half2, 64 per thread
            #pragma unroll
            for (int u = 0; u < 64; u++) {
                int idx = u * 256 + t;
                int r = idx >> 6, n2 = idx & 63;
                int col0 = n2 * 2;
                int cc = col0 >> 3;
                __half2* p = (__half2*)(smem + bOffB
                    + r * 256 + ((cc ^ (r & 7)) << 4) + (col0 & 7) * 2);
                float2 v = __half22float2(*p);
                int h = r >> 5;
                v.x *= normsm[h * 128 + col0];
                v.y *= normsm[h * 128 + col0 + 1];
                *p = __floats2half2_rn(v.x, v.y);
            }
            __syncthreads();
        }

        uint32_t aB = sbase + (uint32_t)buf * ABUF;
        uint32_t bB = sbase + bOffB + (uint32_t)kt * 8192;
        #pragma unroll
        for (int kg = 0; kg < 2; kg++) {
            uint32_t afr[2][4];
            #pragma unroll
            for (int i2 = 0; i2 < 2; i2++)
                ldm_x4(afr[i2], aB + (aAddrF[i2] ^ (kg << 5)));
            uint32_t bfr[4][4];
            #pragma unroll
            for (int j4 = 0; j4 < 4; j4++)
                ldm_x4_trans(bfr[j4], bB + ((bAddrF ^ (j4 << 5)) + (kg << 12)));
            #pragma unroll
            for (int j2 = 0; j2 < 8; j2++) {
                uint32_t b0 = bfr[j2 >> 1][(j2 & 1)];
                uint32_t b1 = bfr[j2 >> 1][(j2 & 1) + 2];
                #pragma unroll
                for (int i2 = 0; i2 < 2; i2++)
                    mma_fp16(acc[i2][j2], afr[i2], b0, b1);
            }
        }

        if (kt == 7) {
            #pragma unroll
            for (int i2 = 0; i2 < 2; i2++) {
                int lr0 = wm * 32 + i2 * 16 + g;
                int o0  = mt2 * 128 + lr0;
                int o1  = o0 + 8;
                float bi0 = bias[o0], bi1 = bias[o1];
                float slo = 0.f, slo2 = 0.f, shi = 0.f, shi2 = 0.f;
                #pragma unroll
                for (int j2 = 0; j2 < 8; j2++) {
                    int lc = wn * 64 + j2 * 8 + 2 * c;
                    float v0 = acc[i2][j2][0] + bi0;
                    float v1 = acc[i2][j2][1] + bi0;
                    float v2 = acc[i2][j2][2] + bi1;
                    float v3 = acc[i2][j2][3] + bi1;
                    if (MODE == 0) {
                        if (o0 < 512) {
                            v0 = (v0 > 0.f) ? (v0 + 1.f) : __expf(v0);
                            v1 = (v1 > 0.f) ? (v1 + 1.f) : __expf(v1);
                        }
                        if (o1 < 512) {
                            v2 = (v2 > 0.f) ? (v2 + 1.f) : __expf(v2);
                            v3 = (v3 > 0.f) ? (v3 + 1.f) : __expf(v3);
                        }
                        __half* Cd = g_qkvh + ((size_t)bz * MQKV + (size_t)mt2 * 128) * NSP
                                   + (size_t)nt * 128;
                        *(__half2*)(Cd + (size_t)lr0 * NSP + lc)       = __floats2half2_rn(v0, v1);
                        *(__half2*)(Cd + (size_t)(lr0 + 8) * NSP + lc) = __floats2half2_rn(v2, v3);
                    } else {
                        __half* Cd = g_projh + ((size_t)bz * CCH + (size_t)mt2 * 128) * NSP
                                   + (size_t)nt * 128;
                        *(__half2*)(Cd + (size_t)lr0 * NSP + lc)       = __floats2half2_rn(v0, v1);
                        *(__half2*)(Cd + (size_t)(lr0 + 8) * NSP + lc) = __floats2half2_rn(v2, v3);
                        slo += v0 + v1;  slo2 += v0 * v0 + v1 * v1;
                        shi += v2 + v3;  shi2 += v2 * v2 + v3 * v3;
                    }
                    #pragma unroll
                    for (int q = 0; q < 4; q++) acc[i2][j2][q] = 0.f;
                }
                if (MODE == 1) {
                    slo = warp_sum(slo);  slo2 = warp_sum(slo2);
                    shi = warp_sum(shi);  shi2 = warp_sum(shi2);
                    if (lane == 0) {
                        int Gi = mt2 * 16 + wm * 4 + i2 * 2;
                        gnacc[wn][Gi * 2]           += slo;
                        gnacc[wn][Gi * 2 + 1]       += slo2;
                        gnacc[wn][(Gi + 1) * 2]     += shi;
                        gnacc[wn][(Gi + 1) * 2 + 1] += shi2;
                    }
                }
            }
        }
    }

    if (MODE == 1) {
        __syncthreads();
        if (t < 64)
            g_gnpart[((size_t)bz * 256 + nt) * 64 + t] = gnacc[0][t] + gnacc[1][t];
    }
}

// ---------------- kv = k·v^T via tensor cores, cp.async 3-stage pipeline ----------------
// grid (16 bh, 32 splits of 1024 seq cols). 4 slices of 256 cols, 3 rotating stages.
#define KVSLICE 16896                 // bytes per tensor per stage (32 rows x 528B)
#define KVSTAGE (2 * KVSLICE)         // k + v
#define KVSMEM  (3 * KVSTAGE)         // 101376

__global__ void __launch_bounds__(256) kv_mma_kernel() {
    extern __shared__ char sm[];
    const uint32_t sb = smem_u32(sm);

    int bh = blockIdx.x, split = blockIdx.y;
    int b = bh >> 3, h = bh & 7;

    const int t = threadIdx.x;
    const int lane = t & 31, w = t >> 5;
    const int g = lane >> 2, c = lane & 3;

    const __half* kbase = g_qkvh + ((size_t)b * MQKV + 256 + h * HD) * NSP + (size_t)split * 1024;
    const __half* vbase = g_qkvh + ((size_t)b * MQKV + 512 + h * HD) * NSP + (size_t)split * 1024;

    auto load_slice = [&](int sl) {
        int st = sl - (sl / 3) * 3;
        uint32_t kd = sb + (uint32_t)st * KVSTAGE;
        uint32_t vd = kd + KVSLICE;
        #pragma unroll
        for (int i = 0; i < 4; i++) {
            int f = t + i * 256;
            int r = f >> 5, c32 = f & 31;
            cp16(kd + (uint32_t)(r * 528 + c32 * 16),
                 kbase + (size_t)r * NSP + sl * 256 + c32 * 8);
            cp16(vd + (uint32_t)(r * 528 + c32 * 16),
                 vbase + (size_t)r * NSP + sl * 256 + c32 * 8);
        }
        cp_commit();
    };
    load_slice(0);
    load_slice(1);

    int row_lo = (lane & 7) + ((lane >> 3) & 1) * 8;
    int ksel = lane >> 4;
    uint32_t kbyte = (uint32_t)(w * 64 + ksel * 16);

    float acc[2][4][4];
    #pragma unroll
    for (int i = 0; i < 2; i++)
        #pragma unroll
        for (int j = 0; j < 4; j++)
            #pragma unroll
            for (int q = 0; q < 4; q++) acc[i][j][q] = 0.f;
    float rsum = 0.f;
    const int rr = t >> 3, seg = t & 7;

    #pragma unroll 1
    for (int sl = 0; sl < 4; sl++) {
        int st = sl - (sl / 3) * 3;
        uint32_t kB = sb + (uint32_t)st * KVSTAGE;
        uint32_t vB = kB + KVSLICE;

        cp_wait1();
        __syncthreads();
        if (sl + 2 < 4) load_slice(sl + 2);
        else            cp_commit();      // empty group keeps wait_group 1 semantics

        // rowsum partial for row rr, cols seg*32.. (accumulated)
        const __half* krow = (const __half*)(sm + (size_t)st * KVSTAGE) + rr * 264;
        #pragma unroll
        for (int j = 0; j < 16; j++) {
            float2 kf = __half22float2(*(const __half2*)(krow + seg * 32 + 2 * j));
            rsum += kf.x + kf.y;
        }

        #pragma unroll
        for (int kg = 0; kg < 2; kg++) {
            uint32_t afr[2][4], bfr[2][4];
            #pragma unroll
            for (int i2 = 0; i2 < 2; i2++)
                ldm_x4(afr[i2], kB + (uint32_t)((i2 * 16 + row_lo) * 528) + kbyte + kg * 32);
            #pragma unroll
            for (int j4 = 0; j4 < 2; j4++)
                ldm_x4(bfr[j4], vB + (uint32_t)((j4 * 16 + row_lo) * 528) + kbyte + kg * 32);
            #pragma unroll
            for (int j = 0; j < 4; j++) {
                uint32_t b0 = bfr[j >> 1][(j & 1)];
                uint32_t b1 = bfr[j >> 1][(j & 1) + 2];
                #pragma unroll
                for (int i2 = 0; i2 < 2; i2++)
                    mma_fp16(acc[i2][j], afr[i2], b0, b1);
            }
        }
    }

    // rowsum reduce (8 segs per row)
    {
        float s = rsum;
        #pragma unroll
        for (int o = 4; o; o >>= 1) s += __shfl_xor_sync(0xffffffffu, s, o);
        if (seg == 0) g_ksump[(split * 16 + bh) * 32 + rr] = s;
    }
    __syncthreads();          // all stage reads done -> reuse smem as reduction buffer

    float* red = (float*)sm;
    #pragma unroll
    for (int i2 = 0; i2 < 2; i2++)
        #pragma unroll
        for (int j = 0; j < 4; j++) {
            int r0 = i2 * 16 + g, cc = j * 8 + 2 * c;
            red[w * 1024 + r0 * 32 + cc]           = acc[i2][j][0];
            red[w * 1024 + r0 * 32 + cc + 1]       = acc[i2][j][1];
            red[w * 1024 + (r0 + 8) * 32 + cc]     = acc[i2][j][2];
            red[w * 1024 + (r0 + 8) * 32 + cc + 1] = acc[i2][j][3];
        }
    __syncthreads();

    #pragma unroll
    for (int u = 0; u < 4; u++) {
        int de = t * 4 + u;
        float s = 0.f;
        #pragma unroll
        for (int ww = 0; ww < 8; ww++) s += red[ww * 1024 + de];
        g_kvpart[((size_t)split * 16 + bh) * 1024 + de] = s;
    }
}

// reduce kv partials + rowsums; apply 1/clip; emit ksumA
__global__ void kvreduce_kernel() {
    int i = blockIdx.x * 256 + threadIdx.x;
    if (i >= 16 * 1024) return;
    int bh = i >> 10, de = i & 1023;
    int d = de >> 5, e = de & 31;
    float rs = 0.f;
    #pragma unroll 8
    for (int sp = 0; sp < KVS; sp++)
        rs += g_ksump[(sp * 16 + bh) * 32 + d];
    float cs = fmaxf(rs, 1e-6f);
    float inv = 1.0f / cs;
    float s = 0.f;
    #pragma unroll 8
    for (int sp = 0; sp < KVS; sp++)
        s += g_kvpart[((size_t)sp * 16 + bh) * 1024 + de];
    g_kv[i] = s * inv;
    if (e == 0) {
        int b = bh >> 3, h = bh & 7;
        g_ksumA[b * CCH + h * HD + d] = rs * inv;
    }
}

// ---------------- W2 = ow @ blockdiag(kv)^T (per batch) ----------------
__global__ void w2prep_kernel(const float* __restrict__ out_w) {
    int o = blockIdx.x, b = blockIdx.y;
    int t = threadIdx.x;
    __shared__ float owrow[256];
    owrow[t] = out_w[o * CCH + t];
    __syncthreads();
    int h = t >> 5, d = t & 31;
    const float* kvp = g_kv + (b * 8 + h) * 1024 + d * 32;
    const float* owp = owrow + h * 32;
    float s = 0.f;
    #pragma unroll
    for (int e = 0; e < 32; e++) s = fmaf(owp[e], kvp[e], s);
    g_w2h[((size_t)b * CCH + o) * CCH + t] = __float2half_rn(s);
}

// ---------------- GN2 finalize ----------------
__global__ void gn_finalize_kernel() {
    int bg = blockIdx.x;
    int b = bg >> 5, gg = bg & 31;
    int t = threadIdx.x;
    float s  = g_gnpart[((size_t)b * 256 + t) * 64 + gg * 2];
    float s2 = g_gnpart[((size_t)b * 256 + t) * 64 + gg * 2 + 1];
    __shared__ float sh[8], sh2[8];
    s = warp_sum(s); s2 = warp_sum(s2);
    int w = t >> 5, l = t & 31;
    if (l == 0) { sh[w] = s; sh2[w] = s2; }
    __syncthreads();
    if (w == 0) {
        s  = (l < 8) ? sh[l]  : 0.f;
        s2 = (l < 8) ? sh2[l] : 0.f;
        s = warp_sum(s); s2 = warp_sum(s2);
        if (l == 0) {
            const float inv = 1.0f / (float)(CPG * NSP);
            float mu  = s * inv;
            float var = s2 * inv - mu * mu;
            g_mu2[bg] = mu;
            g_rstd2[bg] = rsqrtf(var + EPS);
        }
    }
}

// ---------------- final: y = xh + GN2(proj) ----------------
__global__ void final_kernel(const float* __restrict__ ow, const float* __restrict__ ob,
                             float* __restrict__ out) {
    const int n4 = NSP / 4;
    const int total = BATCH * CCH * n4;
    const __half2* ph = (const __half2*)g_projh;
    const __half2* xh = (const __half2*)g_xh;
    for (int i = blockIdx.x * blockDim.x + threadIdx.x; i < total; i += gridDim.x * blockDim.x) {
        int row = i / n4;
        int c = row % CCH, b = row / CCH;
        int g = c / CPG;
        float mu = g_mu2[b * GRP + g], r = g_rstd2[b * GRP + g];
        float sc = r * ow[c];
        float sh = ob[c] - mu * sc;
        float2 x0 = __half22float2(xh[2 * i]);
        float2 x1 = __half22float2(xh[2 * i + 1]);
        float2 p0 = __half22float2(ph[2 * i]);
        float2 p1 = __half22float2(ph[2 * i + 1]);
        float4 o;
        o.x = x0.x + fmaf(p0.x, sc, sh);
        o.y = x0.y + fmaf(p0.y, sc, sh);
        o.z = x1.x + fmaf(p1.x, sc, sh);
        o.w = x1.y + fmaf(p1.y, sc, sh);
        ((float4*)out)[i] = o;
    }
}

// ---------------- launch ----------------
extern "C" void kernel_launch(void* const* d_in, const int* in_sizes, int n_in,
                              void* d_out, int out_size) {
    const float* x      = (const float*)d_in[0];
    const float* norm_w = (const float*)d_in[1];
    const float* norm_b = (const float*)d_in[2];
    const float* qkv_w  = (const float*)d_in[3];
    const float* qkv_b  = (const float*)d_in[4];
    const float* out_w  = (const float*)d_in[5];
    const float* out_b  = (const float*)d_in[6];
    const float* onw    = (const float*)d_in[7];
    const float* onb    = (const float*)d_in[8];
    float* out = (float*)d_out;

    cudaFuncSetAttribute(mma_gemm_kernel<0>, cudaFuncAttributeMaxDynamicSharedMemorySize, GSMEM);
    cudaFuncSetAttribute(mma_gemm_kernel<1>, cudaFuncAttributeMaxDynamicSharedMemorySize, GSMEM);
    cudaFuncSetAttribute(kv_mma_kernel, cudaFuncAttributeMaxDynamicSharedMemorySize, KVSMEM);

    gn_stats0_kernel<<<BATCH * GRP, 256>>>(x);
    prep2_kernel<<<dim3(MQKV, BATCH), 256>>>(qkv_w, qkv_b, norm_w, norm_b);
    mma_gemm_kernel<0><<<dim3(256, 1, BATCH), 256, GSMEM>>>(nullptr);
    kv_mma_kernel<<<dim3(16, KVS), 256, KVSMEM>>>();
    kvreduce_kernel<<<64, 256>>>();
    w2prep_kernel<<<dim3(CCH, BATCH), 256>>>(out_w);
    mma_gemm_kernel<1><<<dim3(256, 1, BATCH), 256, GSMEM>>>(out_b);
    gn_finalize_kernel<<<64, 256>>>();
    final_kernel<<<4096, 256>>>(onw, onb, out);
}

// round 12
// speedup vs baseline: 2.3595x; 1.0961x over previous
#include <cuda_runtime.h>
#include <cuda_fp16.h>
#include <cstdint>

// ---------------- problem constants ----------------
#define BATCH 2
#define CCH   256
#define NHEAD 8
#define HD    32
#define GRP   32
#define CPG   8
#define MQKV  768
#define NSP   32768
#define EPS   1e-5f
#define KVS   32       // kv splits, 1024 seq cols each

// ---------------- static scratch ----------------
__device__ __half g_qkvh[(size_t)BATCH * MQKV * NSP];   // fp16 q|k|v
__device__ __half g_xh[(size_t)BATCH * CCH * NSP];      // fp16 x (raw)
__device__ __half g_projh[(size_t)BATCH * CCH * NSP];   // fp16 proj
__device__ __half g_a2h[(size_t)BATCH * MQKV * CCH];    // folded A' fp16
__device__ __half g_w2h[(size_t)BATCH * CCH * CCH];     // W2 fp16
__device__ float g_mu1[BATCH * GRP];
__device__ float g_rstd1[BATCH * GRP];
__device__ float g_mu2[BATCH * GRP];
__device__ float g_rstd2[BATCH * GRP];
__device__ float g_bias2[BATCH * MQKV];
__device__ float g_ksumA[BATCH * CCH];
__device__ float g_kvpart[(size_t)KVS * 16 * 1024];
__device__ float g_ksump[KVS * 16 * 32];
__device__ float g_kv[BATCH * NHEAD * HD * HD];
__device__ float g_gnpart[(size_t)BATCH * 256 * 64];
__device__ float g_gn1p[BATCH * GRP * 4 * 2];           // gn_stats0 partials

// ---------------- helpers ----------------
__device__ __forceinline__ float warp_sum(float v) {
    #pragma unroll
    for (int o = 16; o; o >>= 1) v += __shfl_xor_sync(0xffffffffu, v, o);
    return v;
}
__device__ __forceinline__ uint32_t smem_u32(const void* p) {
    uint32_t a;
    asm("{ .reg .u64 t; cvta.to.shared.u64 t, %1; cvt.u32.u64 %0, t; }" : "=r"(a) : "l"(p));
    return a;
}
__device__ __forceinline__ void cp16(uint32_t saddr, const void* g) {
    asm volatile("cp.async.cg.shared.global [%0], [%1], 16;" :: "r"(saddr), "l"(g) : "memory");
}
__device__ __forceinline__ void cp_commit() {
    asm volatile("cp.async.commit_group;" ::: "memory");
}
__device__ __forceinline__ void cp_wait1() {
    asm volatile("cp.async.wait_group 1;" ::: "memory");
}
__device__ __forceinline__ void ldm_x4(uint32_t* r, uint32_t addr) {
    asm volatile("ldmatrix.sync.aligned.m8n8.x4.shared.b16 {%0,%1,%2,%3}, [%4];"
        : "=r"(r[0]), "=r"(r[1]), "=r"(r[2]), "=r"(r[3]) : "r"(addr));
}
__device__ __forceinline__ void ldm_x4_trans(uint32_t* r, uint32_t addr) {
    asm volatile("ldmatrix.sync.aligned.m8n8.x4.trans.shared.b16 {%0,%1,%2,%3}, [%4];"
        : "=r"(r[0]), "=r"(r[1]), "=r"(r[2]), "=r"(r[3]) : "r"(addr));
}
__device__ __forceinline__ void mma_fp16(float* c, const uint32_t* a, uint32_t b0, uint32_t b1) {
    asm volatile(
        "mma.sync.aligned.m16n8k16.row.col.f32.f16.f16.f32 "
        "{%0,%1,%2,%3}, {%4,%5,%6,%7}, {%8,%9}, {%0,%1,%2,%3};"
        : "+f"(c[0]), "+f"(c[1]), "+f"(c[2]), "+f"(c[3])
        : "r"(a[0]), "r"(a[1]), "r"(a[2]), "r"(a[3]), "r"(b0), "r"(b1));
}

// ---------------- group-norm stats over x, 4 blocks per group (also emits xh) ------
__global__ void gn_stats0_kernel(const float* __restrict__ xsrc) {
    int grp = blockIdx.x;
    int quarter = blockIdx.y;
    const int M4 = CPG * NSP / 4;          // float4 count per group
    const int Q4 = M4 / 4;                 // per quarter
    const float4* base = (const float4*)(xsrc + (size_t)grp * CPG * NSP) + quarter * Q4;
    uint2* xh4 = (uint2*)(g_xh + (size_t)grp * CPG * NSP) + quarter * Q4;
    float s = 0.f, s2 = 0.f;
    for (int i = threadIdx.x; i < Q4; i += 256) {
        float4 v = base[i];
        s  += (v.x + v.y) + (v.z + v.w);
        s2 += v.x * v.x + v.y * v.y + v.z * v.z + v.w * v.w;
        __half2 h0 = __floats2half2_rn(v.x, v.y);
        __half2 h1 = __floats2half2_rn(v.z, v.w);
        uint2 u;
        u.x = *(uint32_t*)&h0;
        u.y = *(uint32_t*)&h1;
        xh4[i] = u;
    }
    __shared__ float sh[8], sh2[8];
    s = warp_sum(s); s2 = warp_sum(s2);
    int w = threadIdx.x >> 5, l = threadIdx.x & 31;
    if (l == 0) { sh[w] = s; sh2[w] = s2; }
    __syncthreads();
    if (w == 0) {
        s  = (l < 8) ? sh[l]  : 0.f;
        s2 = (l < 8) ? sh2[l] : 0.f;
        s = warp_sum(s); s2 = warp_sum(s2);
        if (l == 0) {
            g_gn1p[(grp * 4 + quarter) * 2]     = s;
            g_gn1p[(grp * 4 + quarter) * 2 + 1] = s2;
        }
    }
}

__global__ void gn1_final_kernel() {
    int grp = threadIdx.x;     // 64 groups
    if (grp >= BATCH * GRP) return;
    float s = 0.f, s2 = 0.f;
    #pragma unroll
    for (int i = 0; i < 4; i++) {
        s  += g_gn1p[(grp * 4 + i) * 2];
        s2 += g_gn1p[(grp * 4 + i) * 2 + 1];
    }
    const float inv = 1.0f / (float)(CPG * NSP);
    float mu  = s * inv;
    float var = s2 * inv - mu * mu;
    g_mu1[grp] = mu;
    g_rstd1[grp] = rsqrtf(var + EPS);
}

// fold GN1 affine into weights: A' = fp16(W*sc), bias' = W@sh + qkv_b
__global__ void prep2_kernel(const float* __restrict__ qkv_w, const float* __restrict__ qkv_b,
                             const float* __restrict__ nw, const float* __restrict__ nb) {
    int o = blockIdx.x, b = blockIdx.y;
    int c = threadIdx.x;
    float mu = g_mu1[b * GRP + c / CPG];
    float r  = g_rstd1[b * GRP + c / CPG];
    float sc = r * nw[c];
    float sh = nb[c] - mu * sc;
    float w  = qkv_w[o * CCH + c];
    g_a2h[((size_t)b * MQKV + o) * CCH + c] = __float2half_rn(w * sc);
    float v = w * sh;
    __shared__ float red[8];
    v = warp_sum(v);
    int wp = c >> 5, l = c & 31;
    if (l == 0) red[wp] = v;
    __syncthreads();
    if (c == 0) {
        float s = 0.f;
        #pragma unroll
        for (int i = 0; i < 8; i++) s += red[i];
        g_bias2[b * MQKV + o] = s + qkv_b[o];
    }
}

// ======== fp16 GEMM: block-resident B (256x128), m-loop, depth-2 A pipeline ========
// MODE 0: A=g_a2h[bz] (6 m-tiles), B=g_xh, C=g_qkvh fp16 (elu rows<512)
// MODE 1: A=g_w2h[bz] (2 m-tiles), B=raw q (normalized in-smem), C=g_projh + GN2 partials
#define ABUF 8192
#define BFULL 65536
#define GSMEM (3 * ABUF + BFULL)

template<int MODE>
__global__ void __launch_bounds__(256, 2) mma_gemm_kernel(const float* __restrict__ bias_arg)
{
    extern __shared__ char smem[];
    const uint32_t sbase = smem_u32(smem);
    const uint32_t bOffB = 3u * ABUF;
    const int MT = (MODE == 0) ? 6 : 2;
    const int NG = MT * 8;

    __shared__ float gnacc[2][64];
    __shared__ float ksA_sm[256];
    __shared__ float normsm[1024];    // rn[h][n], 8 x 128

    const int bz = blockIdx.z;
    const int nt = blockIdx.x;
    const int t  = threadIdx.x;
    const int warp = t >> 5, lane = t & 31;
    const int wm = warp >> 1;
    const int wn = warp & 1;
    const int g  = lane >> 2;
    const int c  = lane & 3;

    const __half* Ab0;
    const __half* Bb;
    const float* bias;
    if (MODE == 0) {
        Ab0  = g_a2h + (size_t)bz * MQKV * CCH;
        bias = g_bias2 + bz * MQKV;
        Bb   = g_xh + (size_t)bz * CCH * NSP + (size_t)nt * 128;
    } else {
        Ab0  = g_w2h + (size_t)bz * CCH * CCH;
        bias = bias_arg;
        Bb   = g_qkvh + (size_t)bz * MQKV * NSP + (size_t)nt * 128;   // raw q rows 0..255
    }

    if (MODE == 1) {
        if (t < 128) gnacc[t >> 6][t & 63] = 0.f;
        ksA_sm[t] = g_ksumA[bz * CCH + t];
    }

    #pragma unroll
    for (int i = 0; i < 16; i++) {
        int f = t + i * 256;
        int k = f >> 4, cc = f & 15;
        cp16(sbase + bOffB + (uint32_t)(k * 256 + ((cc ^ (k & 7)) << 4)),
             Bb + (size_t)k * NSP + cc * 8);
    }
    cp_commit();

    auto load_A = [&](int Gc) {
        int mt2 = Gc >> 3, ch = Gc & 7, buf = Gc - (Gc / 3) * 3;
        const __half* At = Ab0 + (size_t)mt2 * 128 * CCH;
        #pragma unroll
        for (int i = 0; i < 2; i++) {
            int f = t + i * 256;
            int m = f >> 2, k8 = f & 3;
            cp16(sbase + (uint32_t)buf * ABUF + (uint32_t)(m * 64 + ((k8 ^ ((m >> 1) & 3)) << 4)),
                 At + (size_t)m * CCH + ch * 32 + k8 * 8);
        }
        cp_commit();
    };
    load_A(0);
    load_A(1);

    uint32_t aAddrF[2];
    {
        int row_lo = (lane & 7) + ((lane >> 3) & 1) * 8;
        int kc = lane >> 4;
        #pragma unroll
        for (int i2 = 0; i2 < 2; i2++) {
            int row = wm * 32 + i2 * 16 + row_lo;
            aAddrF[i2] = (uint32_t)(row * 64 + ((kc ^ ((row >> 1) & 3)) << 4));
        }
    }
    uint32_t bAddrF;
    {
        int k  = (lane & 7) + ((lane >> 4) << 3);
        int nb = wn * 64 + ((lane >> 3) & 1) * 8;
        int cc = nb >> 3;
        bAddrF = (uint32_t)(k * 256 + ((cc ^ (k & 7)) << 4));
    }

    float acc[2][8][4];
    #pragma unroll
    for (int i = 0; i < 2; i++)
        #pragma unroll
        for (int j = 0; j < 8; j++)
            #pragma unroll
            for (int q = 0; q < 4; q++) acc[i][j][q] = 0.f;

    #pragma unroll 1
    for (int G = 0; G < NG; G++) {
        int kt = G & 7;
        int mt2 = G >> 3;
        int buf = G - (G / 3) * 3;

        cp_wait1();
        __syncthreads();
        if (G + 2 < NG) load_A(G + 2);
        else            cp_commit();

        // ---- MODE 1, first iteration: normalize q panel in smem (half2 pairs) ----
        if (MODE == 1 && G == 0) {
            #pragma unroll
            for (int u = 0; u < 2; u++) {
                int idx = u * 256 + t;           // 0..511 : h*64 + n-pair
                int h = idx >> 6, n2 = idx & 63;
                int col0 = n2 * 2;
                int cc = col0 >> 3, off = (col0 & 7) * 2;
                float sx = 0.f, sy = 0.f;
                #pragma unroll
                for (int d = 0; d < 32; d++) {
                    int r = h * 32 + d;
                    const __half2* p = (const __half2*)(smem + bOffB
                        + r * 256 + ((cc ^ (r & 7)) << 4) + off);
                    float2 v = __half22float2(*p);
                    float ka = ksA_sm[r];
                    sx = fmaf(v.x, ka, sx);
                    sy = fmaf(v.y, ka, sy);
                }
                normsm[h * 128 + col0]     = 1.0f / fmaxf(sx, 1e-6f);
                normsm[h * 128 + col0 + 1] = 1.0f / fmaxf(sy, 1e-6f);
            }
            __syncthreads();
            #pragma unroll
            for (int u = 0; u < 64; u++) {
                int idx = u * 256 + t;
                int r = idx >> 6, n2 = idx & 63;
                int col0 = n2 * 2;
                int cc = col0 >> 3;
                __half2* p = (__half2*)(smem + bOffB
                    + r * 256 + ((cc ^ (r & 7)) << 4) + (col0 & 7) * 2);
                float2 v = __half22float2(*p);
                int h = r >> 5;
                v.x *= normsm[h * 128 + col0];
                v.y *= normsm[h * 128 + col0 + 1];
                *p = __floats2half2_rn(v.x, v.y);
            }
            __syncthreads();
        }

        uint32_t aB = sbase + (uint32_t)buf * ABUF;
        uint32_t bB = sbase + bOffB + (uint32_t)kt * 8192;
        #pragma unroll
        for (int kg = 0; kg < 2; kg++) {
            uint32_t afr[2][4];
            #pragma unroll
            for (int i2 = 0; i2 < 2; i2++)
                ldm_x4(afr[i2], aB + (aAddrF[i2] ^ (kg << 5)));
            uint32_t bfr[4][4];
            #pragma unroll
            for (int j4 = 0; j4 < 4; j4++)
                ldm_x4_trans(bfr[j4], bB + ((bAddrF ^ (j4 << 5)) + (kg << 12)));
            #pragma unroll
            for (int j2 = 0; j2 < 8; j2++) {
                uint32_t b0 = bfr[j2 >> 1][(j2 & 1)];
                uint32_t b1 = bfr[j2 >> 1][(j2 & 1) + 2];
                #pragma unroll
                for (int i2 = 0; i2 < 2; i2++)
                    mma_fp16(acc[i2][j2], afr[i2], b0, b1);
            }
        }

        if (kt == 7) {
            #pragma unroll
            for (int i2 = 0; i2 < 2; i2++) {
                int lr0 = wm * 32 + i2 * 16 + g;
                int o0  = mt2 * 128 + lr0;
                int o1  = o0 + 8;
                float bi0 = bias[o0], bi1 = bias[o1];
                float slo = 0.f, slo2 = 0.f, shi = 0.f, shi2 = 0.f;
                #pragma unroll
                for (int j2 = 0; j2 < 8; j2++) {
                    int lc = wn * 64 + j2 * 8 + 2 * c;
                    float v0 = acc[i2][j2][0] + bi0;
                    float v1 = acc[i2][j2][1] + bi0;
                    float v2 = acc[i2][j2][2] + bi1;
                    float v3 = acc[i2][j2][3] + bi1;
                    if (MODE == 0) {
                        if (o0 < 512) {
                            v0 = (v0 > 0.f) ? (v0 + 1.f) : __expf(v0);
                            v1 = (v1 > 0.f) ? (v1 + 1.f) : __expf(v1);
                        }
                        if (o1 < 512) {
                            v2 = (v2 > 0.f) ? (v2 + 1.f) : __expf(v2);
                            v3 = (v3 > 0.f) ? (v3 + 1.f) : __expf(v3);
                        }
                        __half* Cd = g_qkvh + ((size_t)bz * MQKV + (size_t)mt2 * 128) * NSP
                                   + (size_t)nt * 128;
                        *(__half2*)(Cd + (size_t)lr0 * NSP + lc)       = __floats2half2_rn(v0, v1);
                        *(__half2*)(Cd + (size_t)(lr0 + 8) * NSP + lc) = __floats2half2_rn(v2, v3);
                    } else {
                        __half* Cd = g_projh + ((size_t)bz * CCH + (size_t)mt2 * 128) * NSP
                                   + (size_t)nt * 128;
                        *(__half2*)(Cd + (size_t)lr0 * NSP + lc)       = __floats2half2_rn(v0, v1);
                        *(__half2*)(Cd + (size_t)(lr0 + 8) * NSP + lc) = __floats2half2_rn(v2, v3);
                        slo += v0 + v1;  slo2 += v0 * v0 + v1 * v1;
                        shi += v2 + v3;  shi2 += v2 * v2 + v3 * v3;
                    }
                    #pragma unroll
                    for (int q = 0; q < 4; q++) acc[i2][j2][q] = 0.f;
                }
                if (MODE == 1) {
                    slo = warp_sum(slo);  slo2 = warp_sum(slo2);
                    shi = warp_sum(shi);  shi2 = warp_sum(shi2);
                    if (lane == 0) {
                        int Gi = mt2 * 16 + wm * 4 + i2 * 2;
                        gnacc[wn][Gi * 2]           += slo;
                        gnacc[wn][Gi * 2 + 1]       += slo2;
                        gnacc[wn][(Gi + 1) * 2]     += shi;
                        gnacc[wn][(Gi + 1) * 2 + 1] += shi2;
                    }
                }
            }
        }
    }

    if (MODE == 1) {
        __syncthreads();
        if (t < 64)
            g_gnpart[((size_t)bz * 256 + nt) * 64 + t] = gnacc[0][t] + gnacc[1][t];
    }
}

// ---------------- kv = k·v^T via tensor cores, cp.async 2-stage pipeline ----------------
// grid (16 bh, 32 splits of 1024 seq cols). 4 slices of 256 cols, 2 stages -> 2 blocks/SM.
#define KVSLICE 16896                 // bytes per tensor per stage (32 rows x 528B)
#define KVSTAGE (2 * KVSLICE)         // k + v
#define KVSMEM  (2 * KVSTAGE)         // 67584

__global__ void __launch_bounds__(256, 2) kv_mma_kernel() {
    extern __shared__ char sm[];
    const uint32_t sb = smem_u32(sm);

    int bh = blockIdx.x, split = blockIdx.y;
    int b = bh >> 3, h = bh & 7;

    const int t = threadIdx.x;
    const int lane = t & 31, w = t >> 5;
    const int g = lane >> 2, c = lane & 3;

    const __half* kbase = g_qkvh + ((size_t)b * MQKV + 256 + h * HD) * NSP + (size_t)split * 1024;
    const __half* vbase = g_qkvh + ((size_t)b * MQKV + 512 + h * HD) * NSP + (size_t)split * 1024;

    auto load_slice = [&](int sl) {
        int st = sl & 1;
        uint32_t kd = sb + (uint32_t)st * KVSTAGE;
        uint32_t vd = kd + KVSLICE;
        #pragma unroll
        for (int i = 0; i < 4; i++) {
            int f = t + i * 256;
            int r = f >> 5, c32 = f & 31;
            cp16(kd + (uint32_t)(r * 528 + c32 * 16),
                 kbase + (size_t)r * NSP + sl * 256 + c32 * 8);
            cp16(vd + (uint32_t)(r * 528 + c32 * 16),
                 vbase + (size_t)r * NSP + sl * 256 + c32 * 8);
        }
        cp_commit();
    };
    load_slice(0);
    load_slice(1);

    int row_lo = (lane & 7) + ((lane >> 3) & 1) * 8;
    int ksel = lane >> 4;
    uint32_t kbyte = (uint32_t)(w * 64 + ksel * 16);

    float acc[2][4][4];
    #pragma unroll
    for (int i = 0; i < 2; i++)
        #pragma unroll
        for (int j = 0; j < 4; j++)
            #pragma unroll
            for (int q = 0; q < 4; q++) acc[i][j][q] = 0.f;
    float rsum = 0.f;
    const int rr = t >> 3, seg = t & 7;

    #pragma unroll 1
    for (int sl = 0; sl < 4; sl++) {
        int st = sl & 1;
        uint32_t kB = sb + (uint32_t)st * KVSTAGE;
        uint32_t vB = kB + KVSLICE;

        cp_wait1();               // current stage's load group complete
        __syncthreads();

        // rowsum partial for row rr, cols seg*32.. (accumulated)
        const __half* krow = (const __half*)(sm + (size_t)st * KVSTAGE) + rr * 264;
        #pragma unroll
        for (int j = 0; j < 16; j++) {
            float2 kf = __half22float2(*(const __half2*)(krow + seg * 32 + 2 * j));
            rsum += kf.x + kf.y;
        }

        #pragma unroll
        for (int kg = 0; kg < 2; kg++) {
            uint32_t afr[2][4], bfr[2][4];
            #pragma unroll
            for (int i2 = 0; i2 < 2; i2++)
                ldm_x4(afr[i2], kB + (uint32_t)((i2 * 16 + row_lo) * 528) + kbyte + kg * 32);
            #pragma unroll
            for (int j4 = 0; j4 < 2; j4++)
                ldm_x4(bfr[j4], vB + (uint32_t)((j4 * 16 + row_lo) * 528) + kbyte + kg * 32);
            #pragma unroll
            for (int j = 0; j < 4; j++) {
                uint32_t b0 = bfr[j >> 1][(j & 1)];
                uint32_t b1 = bfr[j >> 1][(j & 1) + 2];
                #pragma unroll
                for (int i2 = 0; i2 < 2; i2++)
                    mma_fp16(acc[i2][j], afr[i2], b0, b1);
            }
        }

        __syncthreads();          // all warps done with this stage before overwrite
        if (sl + 2 < 4) load_slice(sl + 2);
        else            cp_commit();      // empty group keeps wait_group 1 semantics
    }

    // rowsum reduce (8 segs per row)
    {
        float s = rsum;
        #pragma unroll
        for (int o = 4; o; o >>= 1) s += __shfl_xor_sync(0xffffffffu, s, o);
        if (seg == 0) g_ksump[(split * 16 + bh) * 32 + rr] = s;
    }
    __syncthreads();          // all stage reads done -> reuse smem as reduction buffer

    float* red = (float*)sm;
    #pragma unroll
    for (int i2 = 0; i2 < 2; i2++)
        #pragma unroll
        for (int j = 0; j < 4; j++) {
            int r0 = i2 * 16 + g, cc = j * 8 + 2 * c;
            red[w * 1024 + r0 * 32 + cc]           = acc[i2][j][0];
            red[w * 1024 + r0 * 32 + cc + 1]       = acc[i2][j][1];
            red[w * 1024 + (r0 + 8) * 32 + cc]     = acc[i2][j][2];
            red[w * 1024 + (r0 + 8) * 32 + cc + 1] = acc[i2][j][3];
        }
    __syncthreads();

    #pragma unroll
    for (int u = 0; u < 4; u++) {
        int de = t * 4 + u;
        float s = 0.f;
        #pragma unroll
        for (int ww = 0; ww < 8; ww++) s += red[ww * 1024 + de];
        g_kvpart[((size_t)split * 16 + bh) * 1024 + de] = s;
    }
}

// reduce kv partials + rowsums; apply 1/clip; emit ksumA
__global__ void kvreduce_kernel() {
    int i = blockIdx.x * 256 + threadIdx.x;
    if (i >= 16 * 1024) return;
    int bh = i >> 10, de = i & 1023;
    int d = de >> 5, e = de & 31;
    float rs = 0.f;
    #pragma unroll 8
    for (int sp = 0; sp < KVS; sp++)
        rs += g_ksump[(sp * 16 + bh) * 32 + d];
    float cs = fmaxf(rs, 1e-6f);
    float inv = 1.0f / cs;
    float s = 0.f;
    #pragma unroll 8
    for (int sp = 0; sp < KVS; sp++)
        s += g_kvpart[((size_t)sp * 16 + bh) * 1024 + de];
    g_kv[i] = s * inv;
    if (e == 0) {
        int b = bh >> 3, h = bh & 7;
        g_ksumA[b * CCH + h * HD + d] = rs * inv;
    }
}

// ---------------- W2 = ow @ blockdiag(kv)^T (per batch) ----------------
__global__ void w2prep_kernel(const float* __restrict__ out_w) {
    int o = blockIdx.x, b = blockIdx.y;
    int t = threadIdx.x;
    __shared__ float owrow[256];
    owrow[t] = out_w[o * CCH + t];
    __syncthreads();
    int h = t >> 5, d = t & 31;
    const float* kvp = g_kv + (b * 8 + h) * 1024 + d * 32;
    const float* owp = owrow + h * 32;
    float s = 0.f;
    #pragma unroll
    for (int e = 0; e < 32; e++) s = fmaf(owp[e], kvp[e], s);
    g_w2h[((size_t)b * CCH + o) * CCH + t] = __float2half_rn(s);
}

// ---------------- GN2 finalize ----------------
__global__ void gn_finalize_kernel() {
    int bg = blockIdx.x;
    int b = bg >> 5, gg = bg & 31;
    int t = threadIdx.x;
    float s  = g_gnpart[((size_t)b * 256 + t) * 64 + gg * 2];
    float s2 = g_gnpart[((size_t)b * 256 + t) * 64 + gg * 2 + 1];
    __shared__ float sh[8], sh2[8];
    s = warp_sum(s); s2 = warp_sum(s2);
    int w = t >> 5, l = t & 31;
    if (l == 0) { sh[w] = s; sh2[w] = s2; }
    __syncthreads();
    if (w == 0) {
        s  = (l < 8) ? sh[l]  : 0.f;
        s2 = (l < 8) ? sh2[l] : 0.f;
        s = warp_sum(s); s2 = warp_sum(s2);
        if (l == 0) {
            const float inv = 1.0f / (float)(CPG * NSP);
            float mu  = s * inv;
            float var = s2 * inv - mu * mu;
            g_mu2[bg] = mu;
            g_rstd2[bg] = rsqrtf(var + EPS);
        }
    }
}

// ---------------- final: y = xh + GN2(proj) ----------------
__global__ void final_kernel(const float* __restrict__ ow, const float* __restrict__ ob,
                             float* __restrict__ out) {
    const int n4 = NSP / 4;
    const int total = BATCH * CCH * n4;
    const __half2* ph = (const __half2*)g_projh;
    const __half2* xh = (const __half2*)g_xh;
    for (int i = blockIdx.x * blockDim.x + threadIdx.x; i < total; i += gridDim.x * blockDim.x) {
        int row = i / n4;
        int c = row % CCH, b = row / CCH;
        int g = c / CPG;
        float mu = g_mu2[b * GRP + g], r = g_rstd2[b * GRP + g];
        float sc = r * ow[c];
        float sh = ob[c] - mu * sc;
        float2 x0 = __half22float2(xh[2 * i]);
        float2 x1 = __half22float2(xh[2 * i + 1]);
        float2 p0 = __half22float2(ph[2 * i]);
        float2 p1 = __half22float2(ph[2 * i + 1]);
        float4 o;
        o.x = x0.x + fmaf(p0.x, sc, sh);
        o.y = x0.y + fmaf(p0.y, sc, sh);
        o.z = x1.x + fmaf(p1.x, sc, sh);
        o.w = x1.y + fmaf(p1.y, sc, sh);
        ((float4*)out)[i] = o;
    }
}

// ---------------- launch ----------------
extern "C" void kernel_launch(void* const* d_in, const int* in_sizes, int n_in,
                              void* d_out, int out_size) {
    const float* x      = (const float*)d_in[0];
    const float* norm_w = (const float*)d_in[1];
    const float* norm_b = (const float*)d_in[2];
    const float* qkv_w  = (const float*)d_in[3];
    const float* qkv_b  = (const float*)d_in[4];
    const float* out_w  = (const float*)d_in[5];
    const float* out_b  = (const float*)d_in[6];
    const float* onw    = (const float*)d_in[7];
    const float* onb    = (const float*)d_in[8];
    float* out = (float*)d_out;

    cudaFuncSetAttribute(mma_gemm_kernel<0>, cudaFuncAttributeMaxDynamicSharedMemorySize, GSMEM);
    cudaFuncSetAttribute(mma_gemm_kernel<1>, cudaFuncAttributeMaxDynamicSharedMemorySize, GSMEM);
    cudaFuncSetAttribute(kv_mma_kernel, cudaFuncAttributeMaxDynamicSharedMemorySize, KVSMEM);

    gn_stats0_kernel<<<dim3(BATCH * GRP, 4), 256>>>(x);
    gn1_final_kernel<<<1, 64>>>();
    prep2_kernel<<<dim3(MQKV, BATCH), 256>>>(qkv_w, qkv_b, norm_w, norm_b);
    mma_gemm_kernel<0><<<dim3(256, 1, BATCH), 256, GSMEM>>>(nullptr);
    kv_mma_kernel<<<dim3(16, KVS), 256, KVSMEM>>>();
    kvreduce_kernel<<<64, 256>>>();
    w2prep_kernel<<<dim3(CCH, BATCH), 256>>>(out_w);
    mma_gemm_kernel<1><<<dim3(256, 1, BATCH), 256, GSMEM>>>(out_b);
    gn_finalize_kernel<<<64, 256>>>();
    final_kernel<<<4096, 256>>>(onw, onb, out);
}